// round 11
// baseline (speedup 1.0000x reference)
#include <cuda_runtime.h>
#include <cuda_bf16.h>
#include <cstdint>

// Problem constants
#define BATCH 4
#define SEQ   1024
#define HID   2048
#define NHEAD 16
#define NKV   2
#define HD    128
#define TOK   (BATCH*SEQ)          // 4096
#define KVDIM (NKV*HD)             // 256
#define OUT_ELEMS ((size_t)TOK*HID)
#define BUF_ELEMS ((size_t)2*TOK*2*NKV*HD)

// Scratch (device globals — no allocation allowed)
__device__ float g_Q[TOK*HID];
__device__ float g_K[TOK*KVDIM];
__device__ float g_V[TOK*KVDIM];
__device__ float g_A[TOK*HID];

// ---------------------------------------------------------------------------
// bf16 split helpers: x = hi + lo, both bf16; packed (x0 -> lo half, x1 -> hi).
// ---------------------------------------------------------------------------
__device__ __forceinline__ void split_bf16(float x0, float x1,
                                           uint32_t& hi, uint32_t& lo)
{
    asm("cvt.rn.bf16x2.f32 %0, %1, %2;" : "=r"(hi) : "f"(x1), "f"(x0));
    float h0 = __uint_as_float(hi << 16);
    float h1 = __uint_as_float(hi & 0xffff0000u);
    asm("cvt.rn.bf16x2.f32 %0, %1, %2;" : "=r"(lo) : "f"(x1 - h1), "f"(x0 - h0));
}

__device__ __forceinline__ void mma_bf16(float c[4],
    uint32_t a0, uint32_t a1, uint32_t a2, uint32_t a3,
    uint32_t b0, uint32_t b1)
{
    asm volatile(
        "mma.sync.aligned.m16n8k16.row.col.f32.bf16.bf16.f32 "
        "{%0,%1,%2,%3}, {%4,%5,%6,%7}, {%8,%9}, {%0,%1,%2,%3};"
        : "+f"(c[0]), "+f"(c[1]), "+f"(c[2]), "+f"(c[3])
        : "r"(a0), "r"(a1), "r"(a2), "r"(a3), "r"(b0), "r"(b1));
}

// column permutation within one k16 group (8 pairs): pair w -> (w&3)*2 + (w>>2)
// makes frag regs (t4, t4+4) adjacent -> single LDS.64 per reg pair.
__device__ __forceinline__ int colperm(int p) {
    return (p & ~7) + (p & 3)*2 + ((p >> 2) & 1);
}

// ---------------------------------------------------------------------------
// GEMM-NT, bf16 3-pass, pre-split smem.
// Row layout (u32, stride 24): [hi 8][lo 8][pad 8].
// ---------------------------------------------------------------------------
#define KT 16
#define GST 24

__global__ __launch_bounds__(256) void gemm_bf16_kernel(
    const float* __restrict__ A, const float* __restrict__ B,
    const float* __restrict__ bias, float* __restrict__ C,
    int N, int K)
{
    __shared__ __align__(16) uint32_t As[128*GST];
    __shared__ __align__(16) uint32_t Bs[128*GST];

    const int tid  = threadIdx.x;
    const int lane = tid & 31;
    const int wid  = tid >> 5;
    const int g    = lane >> 2;
    const int t4   = lane & 3;
    const int wm   = wid >> 2;
    const int wn   = wid & 3;

    const int m0 = blockIdx.y * 128;
    const int n0 = blockIdx.x * 128;

    const int lrow = tid >> 1;
    const int half = tid & 1;             // 0: pairs 0..3, 1: pairs 4..7
    const float* Ag = A + (size_t)(m0 + lrow) * K + half*8;
    const float* Bg = B + (size_t)(n0 + lrow) * K + half*8;

    float acc[16][4];
#pragma unroll
    for (int i = 0; i < 16; i++)
#pragma unroll
        for (int j = 0; j < 4; j++) acc[i][j] = 0.f;

    float4 pa0 = *(const float4*)(Ag);
    float4 pa1 = *(const float4*)(Ag + 4);
    float4 pb0 = *(const float4*)(Bg);
    float4 pb1 = *(const float4*)(Bg + 4);

    for (int k0 = 0; k0 < K; k0 += KT) {
        // split + commit prefetched tile: pair p = half*4 + j -> col 2j + half
        {
            uint32_t h, l;
            const int base = lrow*GST + half;
            split_bf16(pa0.x, pa0.y, h, l); As[base + 0] = h; As[base + 8 + 0] = l;
            split_bf16(pa0.z, pa0.w, h, l); As[base + 2] = h; As[base + 8 + 2] = l;
            split_bf16(pa1.x, pa1.y, h, l); As[base + 4] = h; As[base + 8 + 4] = l;
            split_bf16(pa1.z, pa1.w, h, l); As[base + 6] = h; As[base + 8 + 6] = l;
            split_bf16(pb0.x, pb0.y, h, l); Bs[base + 0] = h; Bs[base + 8 + 0] = l;
            split_bf16(pb0.z, pb0.w, h, l); Bs[base + 2] = h; Bs[base + 8 + 2] = l;
            split_bf16(pb1.x, pb1.y, h, l); Bs[base + 4] = h; Bs[base + 8 + 4] = l;
            split_bf16(pb1.z, pb1.w, h, l); Bs[base + 6] = h; Bs[base + 8 + 6] = l;
        }
        __syncthreads();

        if (k0 + KT < K) {
            Ag += KT; Bg += KT;
            pa0 = *(const float4*)(Ag);
            pa1 = *(const float4*)(Ag + 4);
            pb0 = *(const float4*)(Bg);
            pb1 = *(const float4*)(Bg + 4);
        }

        uint2 tah[4][2], tal[4][2];
#pragma unroll
        for (int mt = 0; mt < 4; mt++) {
            const uint32_t* ar = As + (wm*64 + mt*16 + g)*GST;
            tah[mt][0] = *(const uint2*)(ar + 2*t4);              // a0,a2 hi
            tah[mt][1] = *(const uint2*)(ar + 8*GST + 2*t4);      // a1,a3 hi
            tal[mt][0] = *(const uint2*)(ar + 8 + 2*t4);          // a0,a2 lo
            tal[mt][1] = *(const uint2*)(ar + 8*GST + 8 + 2*t4);  // a1,a3 lo
        }
#pragma unroll
        for (int nt = 0; nt < 4; nt++) {
            const uint32_t* br = Bs + (wn*32 + nt*8 + g)*GST;
            uint2 bh = *(const uint2*)(br + 2*t4);
            uint2 bl = *(const uint2*)(br + 8 + 2*t4);
#pragma unroll
            for (int mt = 0; mt < 4; mt++) {
                float* c = acc[mt*4 + nt];
                mma_bf16(c, tah[mt][0].x, tah[mt][1].x, tah[mt][0].y, tah[mt][1].y, bh.x, bh.y);
                mma_bf16(c, tah[mt][0].x, tah[mt][1].x, tah[mt][0].y, tah[mt][1].y, bl.x, bl.y);
                mma_bf16(c, tal[mt][0].x, tal[mt][1].x, tal[mt][0].y, tal[mt][1].y, bh.x, bh.y);
            }
        }
        __syncthreads();
    }

#pragma unroll
    for (int mt = 0; mt < 4; mt++) {
#pragma unroll
        for (int nt = 0; nt < 4; nt++) {
            const float* c = acc[mt*4 + nt];
            int row0 = m0 + wm*64 + mt*16 + g;
            int col  = n0 + wn*32 + nt*8 + 2*t4;
            float b0 = bias ? bias[col]     : 0.f;
            float b1 = bias ? bias[col + 1] : 0.f;
            float2 v0 = make_float2(c[0] + b0, c[1] + b1);
            float2 v1 = make_float2(c[2] + b0, c[3] + b1);
            *(float2*)(C + (size_t)row0 * N + col)       = v0;
            *(float2*)(C + (size_t)(row0 + 8) * N + col) = v1;
        }
    }
}

// ---------------------------------------------------------------------------
// RoPE in place on Q and K.
// ---------------------------------------------------------------------------
__global__ void rope_kernel(float* __restrict__ Q, float* __restrict__ K,
                            const float* __restrict__ cosb,
                            const float* __restrict__ sinb)
{
    int t  = blockIdx.x;
    int hy = blockIdx.y;
    int i  = threadIdx.x;
    int s  = t & (SEQ - 1);
    float c  = cosb[s*HD + i];
    float si = sinb[s*HD + i];
    float* p = (hy < NHEAD) ? (Q + (size_t)t*HID + hy*HD)
                            : (K + (size_t)t*KVDIM + (hy - NHEAD)*HD);
    float x1 = p[i], x2 = p[i + 64];
    p[i]      = x1 * c - x2 * si;
    p[i + 64] = x2 * c + x1 * si;
}

// ---------------------------------------------------------------------------
// Scatter K/V into output kv buffer (dtype-sniffing select_index).
// ---------------------------------------------------------------------------
__global__ void scatter_kernel(const float* __restrict__ K,
                               const float* __restrict__ V,
                               const void* __restrict__ idx,
                               float* __restrict__ buf)
{
    int t = blockIdx.x;
    int d = threadIdx.x;
    const long long* i64 = (const long long*)idx;
    const int*       i32 = (const int*)idx;
    bool is64 = ((unsigned long long)i64[1]) < (unsigned long long)(2*TOK);
    long long row = is64 ? i64[t] : (long long)i32[t];
    if (row < 0 || row >= (long long)(2*TOK)) return;
    size_t base = (size_t)row * 4 * HD;
    buf[base + 0*HD + d] = K[(size_t)t*KVDIM + d];
    buf[base + 1*HD + d] = K[(size_t)t*KVDIM + HD + d];
    buf[base + 2*HD + d] = V[(size_t)t*KVDIM + d];
    buf[base + 3*HD + d] = V[(size_t)t*KVDIM + HD + d];
}

// ---------------------------------------------------------------------------
// Tensor-core flash attention, bf16 3-pass, pre-split smem everywhere.
// sq/sk rows: [hi 64 u32][lo 64 u32][pad 8], stride 136.
// sv transposed (row = d, cols = key pairs): [hi 32][lo 32][pad 8], stride 72.
// sp (P, pre-split at write): same 72 layout.
// ---------------------------------------------------------------------------
#define ABM 128
#define ABN 64
#define SQ_ST 136
#define SK_ST 136
#define SV_ST 72
#define SP_ST 72
#define ATTN_SMEM ((ABM*SQ_ST + ABN*SK_ST + ABM*SV_ST + ABM*SP_ST) * sizeof(uint32_t))

__global__ __launch_bounds__(256, 1) void attn_mma_kernel(
    const float* __restrict__ Q, const float* __restrict__ K,
    const float* __restrict__ V, float* __restrict__ Aout)
{
    extern __shared__ __align__(16) uint32_t smu[];
    uint32_t* sq = smu;                   // 128 x 136
    uint32_t* sk = sq + ABM*SQ_ST;        // 64 x 136
    uint32_t* sv = sk + ABN*SK_ST;        // 128 x 72 (d-major, key pairs)
    uint32_t* sp = sv + ABM*SV_ST;        // 128 x 72

    const int bh  = blockIdx.y;
    const int b   = bh / NHEAD;
    const int h   = bh % NHEAD;
    const int kvh = h / (NHEAD / NKV);
    const int qt  = blockIdx.x;
    const int tid = threadIdx.x;
    const int lane = tid & 31;
    const int wid  = tid >> 5;
    const int g    = lane >> 2;
    const int t4   = lane & 3;
    const float scale = 0.08838834764831845f;

    // load + pre-split Q tile (128 x 128 floats = 128 x 64 pairs)
    const float* Qg = Q + (size_t)(b*SEQ + qt*ABM) * HID + h*HD;
    for (int i = tid; i < ABM*32; i += 256) {
        int r = i >> 5, c4 = i & 31;
        float4 v = ((const float4*)(Qg + (size_t)r*HID))[c4];
        uint32_t h0, l0, h1, l1;
        split_bf16(v.x, v.y, h0, l0);
        split_bf16(v.z, v.w, h1, l1);
        int c0 = colperm(2*c4), c1 = colperm(2*c4 + 1);
        sq[r*SQ_ST + c0]      = h0;  sq[r*SQ_ST + 64 + c0] = l0;
        sq[r*SQ_ST + c1]      = h1;  sq[r*SQ_ST + 64 + c1] = l1;
    }

    float o[16][4];
#pragma unroll
    for (int i = 0; i < 16; i++)
#pragma unroll
        for (int j = 0; j < 4; j++) o[i][j] = 0.f;
    float mrow[2] = {-1e30f, -1e30f};
    float lrow[2] = {0.f, 0.f};

    const int qrow_base = qt*ABM + wid*16;
    const int nkt = 2*qt + 2;

    for (int kt = 0; kt < nkt; kt++) {
        __syncthreads();
        const float* Kg = K + (size_t)(b*SEQ + kt*ABN) * KVDIM + kvh*HD;
        const float* Vg = V + (size_t)(b*SEQ + kt*ABN) * KVDIM + kvh*HD;
        // K: 64 rows x 32 float4
        for (int i = tid; i < ABN*32; i += 256) {
            int r = i >> 5, c4 = i & 31;
            float4 v = ((const float4*)(Kg + (size_t)r*KVDIM))[c4];
            uint32_t h0, l0, h1, l1;
            split_bf16(v.x, v.y, h0, l0);
            split_bf16(v.z, v.w, h1, l1);
            int c0 = colperm(2*c4), c1 = colperm(2*c4 + 1);
            sk[r*SK_ST + c0]      = h0;  sk[r*SK_ST + 64 + c0] = l0;
            sk[r*SK_ST + c1]      = h1;  sk[r*SK_ST + 64 + c1] = l1;
        }
        // V transposed: thread handles (key-pair kp, d-pair d2)
        for (int i = tid; i < 32*64; i += 256) {
            int kp = i >> 6, d2 = i & 63;
            float2 v0 = *(const float2*)(Vg + (size_t)(2*kp  )*KVDIM + 2*d2);
            float2 v1 = *(const float2*)(Vg + (size_t)(2*kp+1)*KVDIM + 2*d2);
            uint32_t ha, la, hb, lb;
            split_bf16(v0.x, v1.x, ha, la);   // d = 2*d2   : (key 2kp, key 2kp+1)
            split_bf16(v0.y, v1.y, hb, lb);   // d = 2*d2+1
            int cp = colperm(kp & 31) + (kp >> 5)*0; // kp in 0..31, one group of 4 k16-groups
            // colperm over kp (0..31): group kp>>3, within w=kp&7
            cp = (kp & ~7) + (kp & 3)*2 + ((kp >> 2) & 1);
            sv[(2*d2  )*SV_ST + cp]      = ha;  sv[(2*d2  )*SV_ST + 32 + cp] = la;
            sv[(2*d2+1)*SV_ST + cp]      = hb;  sv[(2*d2+1)*SV_ST + 32 + cp] = lb;
        }
        __syncthreads();

        const int kcol_base = kt*ABN;
        if (kcol_base > qrow_base + 15) continue;

        // ---- S = Q K^T (warp stripe 16 x 64) ----
        float sacc[8][4];
#pragma unroll
        for (int i = 0; i < 8; i++)
#pragma unroll
            for (int j = 0; j < 4; j++) sacc[i][j] = 0.f;

#pragma unroll
        for (int kk = 0; kk < HD/16; kk++) {
            const uint32_t* qr = sq + (wid*16 + g)*SQ_ST + kk*8 + 2*t4;
            uint2 ah02 = *(const uint2*)(qr);
            uint2 ah13 = *(const uint2*)(qr + 8*SQ_ST);
            uint2 al02 = *(const uint2*)(qr + 64);
            uint2 al13 = *(const uint2*)(qr + 8*SQ_ST + 64);
#pragma unroll
            for (int nt = 0; nt < 8; nt++) {
                const uint32_t* kr = sk + (nt*8 + g)*SK_ST + kk*8 + 2*t4;
                uint2 bh = *(const uint2*)(kr);
                uint2 bl = *(const uint2*)(kr + 64);
                float* c = sacc[nt];
                mma_bf16(c, ah02.x, ah13.x, ah02.y, ah13.y, bh.x, bh.y);
                mma_bf16(c, ah02.x, ah13.x, ah02.y, ah13.y, bl.x, bl.y);
                mma_bf16(c, al02.x, al13.x, al02.y, al13.y, bh.x, bh.y);
            }
        }

        // ---- mask + online softmax (warp-local); P pre-split at write ----
        const bool need_mask = (kcol_base + ABN - 1) > qrow_base;
        float alpha2[2];
#pragma unroll
        for (int hh = 0; hh < 2; hh++) {
            const int qg = qrow_base + g + 8*hh;
            float mx = -1e30f;
#pragma unroll
            for (int nt = 0; nt < 8; nt++) {
#pragma unroll
                for (int j = 0; j < 2; j++) {
                    float s = sacc[nt][2*hh + j] * scale;
                    if (need_mask) {
                        int kg = kcol_base + nt*8 + 2*t4 + j;
                        if (kg > qg) s = -1e30f;
                    }
                    sacc[nt][2*hh + j] = s;
                    mx = fmaxf(mx, s);
                }
            }
            mx = fmaxf(mx, __shfl_xor_sync(0xffffffffu, mx, 1));
            mx = fmaxf(mx, __shfl_xor_sync(0xffffffffu, mx, 2));
            float mnew = fmaxf(mrow[hh], mx);
            float alpha = __expf(mrow[hh] - mnew);
            float sum = 0.f;
            const int prow = (wid*16 + g + 8*hh)*SP_ST;
#pragma unroll
            for (int nt = 0; nt < 8; nt++) {
                float p0 = __expf(sacc[nt][2*hh]     - mnew);
                float p1 = __expf(sacc[nt][2*hh + 1] - mnew);
                uint32_t hv, lv;
                split_bf16(p0, p1, hv, lv);
                // pair index pp = nt*4 + t4 -> col = (nt>>1)*8 + t4*2 + (nt&1)
                int cp = (nt >> 1)*8 + t4*2 + (nt & 1);
                sp[prow + cp]      = hv;
                sp[prow + 32 + cp] = lv;
                sum += p0 + p1;
            }
            sum += __shfl_xor_sync(0xffffffffu, sum, 1);
            sum += __shfl_xor_sync(0xffffffffu, sum, 2);
            lrow[hh] = lrow[hh]*alpha + sum;
            mrow[hh] = mnew;
            alpha2[hh] = alpha;
        }

#pragma unroll
        for (int nt = 0; nt < 16; nt++) {
            o[nt][0] *= alpha2[0]; o[nt][1] *= alpha2[0];
            o[nt][2] *= alpha2[1]; o[nt][3] *= alpha2[1];
        }

        __syncwarp();   // sp is warp-private; order writes vs frag reads

        // ---- O += P V ----
#pragma unroll
        for (int kk = 0; kk < ABN/16; kk++) {
            const uint32_t* pr = sp + (wid*16 + g)*SP_ST + kk*8 + 2*t4;
            uint2 ah02 = *(const uint2*)(pr);
            uint2 ah13 = *(const uint2*)(pr + 8*SP_ST);
            uint2 al02 = *(const uint2*)(pr + 32);
            uint2 al13 = *(const uint2*)(pr + 8*SP_ST + 32);
#pragma unroll
            for (int nt = 0; nt < 16; nt++) {
                const uint32_t* vr = sv + (nt*8 + g)*SV_ST + kk*8 + 2*t4;
                uint2 bh = *(const uint2*)(vr);
                uint2 bl = *(const uint2*)(vr + 32);
                float* c = o[nt];
                mma_bf16(c, ah02.x, ah13.x, ah02.y, ah13.y, bh.x, bh.y);
                mma_bf16(c, ah02.x, ah13.x, ah02.y, ah13.y, bl.x, bl.y);
                mma_bf16(c, al02.x, al13.x, al02.y, al13.y, bh.x, bh.y);
            }
        }
    }

    // epilogue
    const float inv0 = 1.f / lrow[0];
    const float inv1 = 1.f / lrow[1];
    const int r0 = qt*ABM + wid*16 + g;
    float* Ag0 = Aout + (size_t)(b*SEQ + r0) * HID + h*HD;
    float* Ag1 = Ag0 + 8*(size_t)HID;
#pragma unroll
    for (int nt = 0; nt < 16; nt++) {
        int col = nt*8 + 2*t4;
        *(float2*)(Ag0 + col) = make_float2(o[nt][0]*inv0, o[nt][1]*inv0);
        *(float2*)(Ag1 + col) = make_float2(o[nt][2]*inv1, o[nt][3]*inv1);
    }
}

// ---------------------------------------------------------------------------
// Launch.
// ---------------------------------------------------------------------------
extern "C" void kernel_launch(void* const* d_in, const int* in_sizes, int n_in,
                              void* d_out, int out_size)
{
    const void* slot[12];
    if (n_in >= 12 && in_sizes[0] == (int)(TOK*(size_t)HID)) {
        for (int i = 0; i < 12; i++) slot[i] = d_in[i];
    } else {
        // alphabetical: cos,k_b,k_w,kv_buffer,o_w,q_b,q_w,select_index,sin,v_b,v_w,x
        slot[8]  = d_in[0];
        slot[4]  = d_in[1];
        slot[3]  = d_in[2];
        slot[10] = d_in[3];
        slot[7]  = d_in[4];
        slot[2]  = d_in[5];
        slot[1]  = d_in[6];
        slot[11] = d_in[7];
        slot[9]  = d_in[8];
        slot[6]  = d_in[9];
        slot[5]  = d_in[10];
        slot[0]  = d_in[11];
    }

    const float* x     = (const float*)slot[0];
    const float* q_w   = (const float*)slot[1];
    const float* q_b   = (const float*)slot[2];
    const float* k_w   = (const float*)slot[3];
    const float* k_b   = (const float*)slot[4];
    const float* v_w   = (const float*)slot[5];
    const float* v_b   = (const float*)slot[6];
    const float* o_w   = (const float*)slot[7];
    const float* cosb  = (const float*)slot[8];
    const float* sinb  = (const float*)slot[9];
    const float* kvbuf = (const float*)slot[10];
    const void*  sel   = slot[11];

    float* out = (float*)d_out;
    bool has_buf = (size_t)out_size >= OUT_ELEMS + BUF_ELEMS;
    float* buf_out = out + ((size_t)out_size - BUF_ELEMS);

    float *Q, *K, *V, *A;
    cudaGetSymbolAddress((void**)&Q, g_Q);
    cudaGetSymbolAddress((void**)&K, g_K);
    cudaGetSymbolAddress((void**)&V, g_V);
    cudaGetSymbolAddress((void**)&A, g_A);

    // QKV projections
    gemm_bf16_kernel<<<dim3(HID/128, TOK/128), 256>>>(x, q_w, q_b, Q, HID, HID);
    gemm_bf16_kernel<<<dim3(KVDIM/128, TOK/128), 256>>>(x, k_w, k_b, K, KVDIM, HID);
    gemm_bf16_kernel<<<dim3(KVDIM/128, TOK/128), 256>>>(x, v_w, v_b, V, KVDIM, HID);

    // RoPE on Q and K (in place)
    rope_kernel<<<dim3(TOK, NHEAD + NKV), 64>>>(Q, K, cosb, sinb);

    // KV buffer output
    if (has_buf) {
        cudaMemcpyAsync(buf_out, kvbuf, BUF_ELEMS * sizeof(float),
                        cudaMemcpyDeviceToDevice);
        scatter_kernel<<<TOK, 128>>>(K, V, sel, buf_out);
    }

    // Attention
    cudaFuncSetAttribute(attn_mma_kernel,
                         cudaFuncAttributeMaxDynamicSharedMemorySize,
                         (int)ATTN_SMEM);
    attn_mma_kernel<<<dim3(SEQ/ABM, BATCH*NHEAD), 256, ATTN_SMEM>>>(Q, K, V, A);

    // Output projection
    gemm_bf16_kernel<<<dim3(HID/128, TOK/128), 256>>>(A, o_w, nullptr, out, HID, HID);
}

// round 12
// speedup vs baseline: 1.2695x; 1.2695x over previous
#include <cuda_runtime.h>
#include <cuda_bf16.h>
#include <cstdint>

// Problem constants
#define BATCH 4
#define SEQ   1024
#define HID   2048
#define NHEAD 16
#define NKV   2
#define HD    128
#define TOK   (BATCH*SEQ)          // 4096
#define KVDIM (NKV*HD)             // 256
#define OUT_ELEMS ((size_t)TOK*HID)
#define BUF_ELEMS ((size_t)2*TOK*2*NKV*HD)

// Scratch (device globals — no allocation allowed)
__device__ float g_Q[TOK*HID];
__device__ float g_K[TOK*KVDIM];
__device__ float g_V[TOK*KVDIM];
__device__ float g_A[TOK*HID];
// pre-split (packed bf16 hi|lo) operands, same byte size as the fp32 originals
__device__ uint32_t g_xs[TOK*HID];
__device__ uint32_t g_qws[HID*HID];
__device__ uint32_t g_kws[KVDIM*HID];
__device__ uint32_t g_vws[KVDIM*HID];
__device__ uint32_t g_ows[HID*HID];
__device__ uint32_t g_As[TOK*HID];

// ---------------------------------------------------------------------------
// bf16 split helpers: x = hi + lo, both bf16; packed (x0 -> lo half, x1 -> hi).
// ---------------------------------------------------------------------------
__device__ __forceinline__ void split_bf16(float x0, float x1,
                                           uint32_t& hi, uint32_t& lo)
{
    asm("cvt.rn.bf16x2.f32 %0, %1, %2;" : "=r"(hi) : "f"(x1), "f"(x0));
    float h0 = __uint_as_float(hi << 16);
    float h1 = __uint_as_float(hi & 0xffff0000u);
    asm("cvt.rn.bf16x2.f32 %0, %1, %2;" : "=r"(lo) : "f"(x1 - h1), "f"(x0 - h0));
}

__device__ __forceinline__ void mma_bf16(float c[4],
    uint32_t a0, uint32_t a1, uint32_t a2, uint32_t a3,
    uint32_t b0, uint32_t b1)
{
    asm volatile(
        "mma.sync.aligned.m16n8k16.row.col.f32.bf16.bf16.f32 "
        "{%0,%1,%2,%3}, {%4,%5,%6,%7}, {%8,%9}, {%0,%1,%2,%3};"
        : "+f"(c[0]), "+f"(c[1]), "+f"(c[2]), "+f"(c[3])
        : "r"(a0), "r"(a1), "r"(a2), "r"(a3), "r"(b0), "r"(b1));
}

__device__ __forceinline__ void cpa16(uint32_t smem_addr, const void* gptr) {
    asm volatile("cp.async.ca.shared.global [%0], [%1], 16;\n"
                 :: "r"(smem_addr), "l"(gptr));
}

// ---------------------------------------------------------------------------
// Pre-split kernel: fp32 row-major [rows x 2048] -> packed hi/lo layout.
// Per k16 group (16 floats = 8 pairs): words [hi p0..p7][lo p0..p7].
// Each thread handles 8 consecutive floats (half a group) -> 2 uint4 stores.
// ---------------------------------------------------------------------------
__global__ void presplit_kernel(const float* __restrict__ src,
                                uint32_t* __restrict__ dst, int n8)
{
    int idx = blockIdx.x * blockDim.x + threadIdx.x;
    if (idx >= n8) return;
    const float4 v0 = *(const float4*)(src + (size_t)idx*8);
    const float4 v1 = *(const float4*)(src + (size_t)idx*8 + 4);
    uint4 h, l;
    split_bf16(v0.x, v0.y, h.x, l.x);
    split_bf16(v0.z, v0.w, h.y, l.y);
    split_bf16(v1.x, v1.y, h.z, l.z);
    split_bf16(v1.z, v1.w, h.w, l.w);
    size_t base = (size_t)(idx >> 1)*16 + (idx & 1)*4;
    *(uint4*)(dst + base)     = h;
    *(uint4*)(dst + base + 8) = l;
}

// ---------------------------------------------------------------------------
// GEMM-NT on pre-split operands: C[m,n] = sum_k A[m,k]*B[n,k] (+bias)
// Block 128x128, ktile 16, 8 warps (2x4), 2-stage cp.async pipeline.
// smem row (u32, stride 24): [hi 8][lo 8][pad 8]. Zero splits in hot loop.
// blockIdx.z selects operand set (for fused K/V projection).
// ---------------------------------------------------------------------------
#define GST 24
#define NK_TILES (HID/16)   // K = 2048 always

__global__ __launch_bounds__(256) void gemm_ps_kernel(
    const uint32_t* __restrict__ A,
    const uint32_t* __restrict__ B0, const float* __restrict__ bias0,
    float* __restrict__ C0,
    const uint32_t* __restrict__ B1, const float* __restrict__ bias1,
    float* __restrict__ C1,
    int N)
{
    __shared__ __align__(16) uint32_t As[2][128*GST];
    __shared__ __align__(16) uint32_t Bs[2][128*GST];

    const uint32_t* B   = blockIdx.z ? B1   : B0;
    const float*    bias= blockIdx.z ? bias1: bias0;
    float*          C   = blockIdx.z ? C1   : C0;

    const int tid  = threadIdx.x;
    const int lane = tid & 31;
    const int wid  = tid >> 5;
    const int g    = lane >> 2;
    const int t4   = lane & 3;
    const int wm   = wid >> 2;
    const int wn   = wid & 3;

    const int m0 = blockIdx.y * 128;
    const int n0 = blockIdx.x * 128;
    const int K  = HID;

    // chunk mapping for tile commit: 512 uint4 chunks per array
    const int ch0 = tid, ch1 = tid + 256;
    const int r0c = ch0 >> 2, q0c = (ch0 & 3)*4;
    const int r1c = ch1 >> 2, q1c = (ch1 & 3)*4;

    float acc[16][4];
#pragma unroll
    for (int i = 0; i < 16; i++)
#pragma unroll
        for (int j = 0; j < 4; j++) acc[i][j] = 0.f;

    // issue stage s for k-group gi
    auto issue = [&](int s, int gi) {
        const uint32_t* Ag = A + (size_t)(m0 + r0c)*K + gi*16 + q0c;
        const uint32_t* Bg = B + (size_t)(n0 + r0c)*K + gi*16 + q0c;
        uint32_t da0 = (uint32_t)__cvta_generic_to_shared(&As[s][r0c*GST + q0c]);
        uint32_t db0 = (uint32_t)__cvta_generic_to_shared(&Bs[s][r0c*GST + q0c]);
        cpa16(da0, Ag);
        cpa16(db0, Bg);
        const uint32_t* Ag1 = A + (size_t)(m0 + r1c)*K + gi*16 + q1c;
        const uint32_t* Bg1 = B + (size_t)(n0 + r1c)*K + gi*16 + q1c;
        uint32_t da1 = (uint32_t)__cvta_generic_to_shared(&As[s][r1c*GST + q1c]);
        uint32_t db1 = (uint32_t)__cvta_generic_to_shared(&Bs[s][r1c*GST + q1c]);
        cpa16(da1, Ag1);
        cpa16(db1, Bg1);
        asm volatile("cp.async.commit_group;\n" ::: "memory");
    };

    issue(0, 0);

    for (int it = 0; it < NK_TILES; it++) {
        const int cur = it & 1;
        if (it + 1 < NK_TILES) {
            issue(cur ^ 1, it + 1);
            asm volatile("cp.async.wait_group 1;\n" ::: "memory");
        } else {
            asm volatile("cp.async.wait_group 0;\n" ::: "memory");
        }
        __syncthreads();

        const uint32_t* Asc = As[cur];
        const uint32_t* Bsc = Bs[cur];

        uint2 tah[4][2], tal[4][2];
#pragma unroll
        for (int mt = 0; mt < 4; mt++) {
            const uint32_t* ar = Asc + (wm*64 + mt*16 + g)*GST;
            tah[mt][0] = *(const uint2*)(ar + 2*t4);
            tah[mt][1] = *(const uint2*)(ar + 8*GST + 2*t4);
            tal[mt][0] = *(const uint2*)(ar + 8 + 2*t4);
            tal[mt][1] = *(const uint2*)(ar + 8*GST + 8 + 2*t4);
        }
#pragma unroll
        for (int nt = 0; nt < 4; nt++) {
            const uint32_t* br = Bsc + (wn*32 + nt*8 + g)*GST;
            uint2 bh = *(const uint2*)(br + 2*t4);
            uint2 bl = *(const uint2*)(br + 8 + 2*t4);
#pragma unroll
            for (int mt = 0; mt < 4; mt++) {
                float* c = acc[mt*4 + nt];
                mma_bf16(c, tah[mt][0].x, tah[mt][1].x, tah[mt][0].y, tah[mt][1].y, bh.x, bh.y);
                mma_bf16(c, tah[mt][0].x, tah[mt][1].x, tah[mt][0].y, tah[mt][1].y, bl.x, bl.y);
                mma_bf16(c, tal[mt][0].x, tal[mt][1].x, tal[mt][0].y, tal[mt][1].y, bh.x, bh.y);
            }
        }
        __syncthreads();
    }

#pragma unroll
    for (int mt = 0; mt < 4; mt++) {
#pragma unroll
        for (int nt = 0; nt < 4; nt++) {
            const float* c = acc[mt*4 + nt];
            int row0 = m0 + wm*64 + mt*16 + g;
            int col  = n0 + wn*32 + nt*8 + 2*t4;
            float b0 = bias ? bias[col]     : 0.f;
            float b1 = bias ? bias[col + 1] : 0.f;
            float2 v0 = make_float2(c[0] + b0, c[1] + b1);
            float2 v1 = make_float2(c[2] + b0, c[3] + b1);
            *(float2*)(C + (size_t)row0 * N + col)       = v0;
            *(float2*)(C + (size_t)(row0 + 8) * N + col) = v1;
        }
    }
}

// ---------------------------------------------------------------------------
// RoPE in place on Q and K.
// ---------------------------------------------------------------------------
__global__ void rope_kernel(float* __restrict__ Q, float* __restrict__ K,
                            const float* __restrict__ cosb,
                            const float* __restrict__ sinb)
{
    int t  = blockIdx.x;
    int hy = blockIdx.y;
    int i  = threadIdx.x;
    int s  = t & (SEQ - 1);
    float c  = cosb[s*HD + i];
    float si = sinb[s*HD + i];
    float* p = (hy < NHEAD) ? (Q + (size_t)t*HID + hy*HD)
                            : (K + (size_t)t*KVDIM + (hy - NHEAD)*HD);
    float x1 = p[i], x2 = p[i + 64];
    p[i]      = x1 * c - x2 * si;
    p[i + 64] = x2 * c + x1 * si;
}

// ---------------------------------------------------------------------------
// Scatter K/V into output kv buffer (dtype-sniffing select_index).
// ---------------------------------------------------------------------------
__global__ void scatter_kernel(const float* __restrict__ K,
                               const float* __restrict__ V,
                               const void* __restrict__ idx,
                               float* __restrict__ buf)
{
    int t = blockIdx.x;
    int d = threadIdx.x;
    const long long* i64 = (const long long*)idx;
    const int*       i32 = (const int*)idx;
    bool is64 = ((unsigned long long)i64[1]) < (unsigned long long)(2*TOK);
    long long row = is64 ? i64[t] : (long long)i32[t];
    if (row < 0 || row >= (long long)(2*TOK)) return;
    size_t base = (size_t)row * 4 * HD;
    buf[base + 0*HD + d] = K[(size_t)t*KVDIM + d];
    buf[base + 1*HD + d] = K[(size_t)t*KVDIM + HD + d];
    buf[base + 2*HD + d] = V[(size_t)t*KVDIM + d];
    buf[base + 3*HD + d] = V[(size_t)t*KVDIM + HD + d];
}

// ---------------------------------------------------------------------------
// Tensor-core flash attention (R10 version, unchanged): bf16 3-pass m16n8k16,
// BM=128 x BN=64, 8 warps, warp-local online softmax.
// ---------------------------------------------------------------------------
#define ABM 128
#define ABN 64
#define SQ_ST 136
#define SK_ST 136
#define SV_ST 132
#define SP_ST 72
#define ATTN_SMEM ((ABM*SQ_ST + ABN*SK_ST + ABN*SV_ST + ABM*SP_ST) * sizeof(float))

__global__ __launch_bounds__(256, 1) void attn_mma_kernel(
    const float* __restrict__ Q, const float* __restrict__ K,
    const float* __restrict__ V, float* __restrict__ Aout)
{
    extern __shared__ float sm[];
    float* sq = sm;
    float* sk = sq + ABM*SQ_ST;
    float* sv = sk + ABN*SK_ST;
    float* sp = sv + ABN*SV_ST;

    const int bh  = blockIdx.y;
    const int b   = bh / NHEAD;
    const int h   = bh % NHEAD;
    const int kvh = h / (NHEAD / NKV);
    const int qt  = blockIdx.x;
    const int tid = threadIdx.x;
    const int lane = tid & 31;
    const int wid  = tid >> 5;
    const int g    = lane >> 2;
    const int t4   = lane & 3;
    const float scale = 0.08838834764831845f;

    const float* Qg = Q + (size_t)(b*SEQ + qt*ABM) * HID + h*HD;
    for (int i = tid; i < ABM*32; i += 256) {
        int r = i >> 5, c = i & 31;
        ((float4*)(sq + r*SQ_ST))[c] = ((const float4*)(Qg + (size_t)r*HID))[c];
    }

    float o[16][4];
#pragma unroll
    for (int i = 0; i < 16; i++)
#pragma unroll
        for (int j = 0; j < 4; j++) o[i][j] = 0.f;
    float mrow[2] = {-1e30f, -1e30f};
    float lrow[2] = {0.f, 0.f};

    const int qrow_base = qt*ABM + wid*16;
    const int nkt = 2*qt + 2;

    for (int kt = 0; kt < nkt; kt++) {
        __syncthreads();
        const float* Kg = K + (size_t)(b*SEQ + kt*ABN) * KVDIM + kvh*HD;
        const float* Vg = V + (size_t)(b*SEQ + kt*ABN) * KVDIM + kvh*HD;
        for (int i = tid; i < ABN*32; i += 256) {
            int r = i >> 5, c = i & 31;
            ((float4*)(sk + r*SK_ST))[c] = ((const float4*)(Kg + (size_t)r*KVDIM))[c];
            ((float4*)(sv + r*SV_ST))[c] = ((const float4*)(Vg + (size_t)r*KVDIM))[c];
        }
        __syncthreads();

        const int kcol_base = kt*ABN;
        if (kcol_base > qrow_base + 15) continue;

        float sacc[8][4];
#pragma unroll
        for (int i = 0; i < 8; i++)
#pragma unroll
            for (int j = 0; j < 4; j++) sacc[i][j] = 0.f;

#pragma unroll
        for (int kk = 0; kk < HD/16; kk++) {
            uint32_t ah[4], al[4];
            {
                int rb  = (wid*16 + g)*SQ_ST + kk*16;
                int rb8 = rb + 8*SQ_ST;
                float2 x0 = *(const float2*)&sq[rb  + 2*t4];
                float2 x1 = *(const float2*)&sq[rb8 + 2*t4];
                float2 x2 = *(const float2*)&sq[rb  + 2*t4 + 8];
                float2 x3 = *(const float2*)&sq[rb8 + 2*t4 + 8];
                split_bf16(x0.x, x0.y, ah[0], al[0]);
                split_bf16(x1.x, x1.y, ah[1], al[1]);
                split_bf16(x2.x, x2.y, ah[2], al[2]);
                split_bf16(x3.x, x3.y, ah[3], al[3]);
            }
#pragma unroll
            for (int nt = 0; nt < 8; nt++) {
                int kb = (nt*8 + g)*SK_ST + kk*16;
                float2 y0 = *(const float2*)&sk[kb + 2*t4];
                float2 y1 = *(const float2*)&sk[kb + 2*t4 + 8];
                uint32_t bh0, bl0, bh1, bl1;
                split_bf16(y0.x, y0.y, bh0, bl0);
                split_bf16(y1.x, y1.y, bh1, bl1);
                float* c = sacc[nt];
                mma_bf16(c, ah[0], ah[1], ah[2], ah[3], bh0, bh1);
                mma_bf16(c, ah[0], ah[1], ah[2], ah[3], bl0, bl1);
                mma_bf16(c, al[0], al[1], al[2], al[3], bh0, bh1);
            }
        }

        const bool need_mask = (kcol_base + ABN - 1) > qrow_base;
        float alpha2[2];
#pragma unroll
        for (int hh = 0; hh < 2; hh++) {
            const int qg = qrow_base + g + 8*hh;
            float mx = -1e30f;
#pragma unroll
            for (int nt = 0; nt < 8; nt++) {
#pragma unroll
                for (int j = 0; j < 2; j++) {
                    float s = sacc[nt][2*hh + j] * scale;
                    if (need_mask) {
                        int kg = kcol_base + nt*8 + 2*t4 + j;
                        if (kg > qg) s = -1e30f;
                    }
                    sacc[nt][2*hh + j] = s;
                    mx = fmaxf(mx, s);
                }
            }
            mx = fmaxf(mx, __shfl_xor_sync(0xffffffffu, mx, 1));
            mx = fmaxf(mx, __shfl_xor_sync(0xffffffffu, mx, 2));
            float mnew = fmaxf(mrow[hh], mx);
            float alpha = __expf(mrow[hh] - mnew);
            float sum = 0.f;
            const int prow = (wid*16 + g + 8*hh)*SP_ST;
#pragma unroll
            for (int nt = 0; nt < 8; nt++) {
                float p0 = __expf(sacc[nt][2*hh]     - mnew);
                float p1 = __expf(sacc[nt][2*hh + 1] - mnew);
                *(float2*)(sp + prow + nt*8 + 2*t4) = make_float2(p0, p1);
                sum += p0 + p1;
            }
            sum += __shfl_xor_sync(0xffffffffu, sum, 1);
            sum += __shfl_xor_sync(0xffffffffu, sum, 2);
            lrow[hh] = lrow[hh]*alpha + sum;
            mrow[hh] = mnew;
            alpha2[hh] = alpha;
        }

#pragma unroll
        for (int nt = 0; nt < 16; nt++) {
            o[nt][0] *= alpha2[0]; o[nt][1] *= alpha2[0];
            o[nt][2] *= alpha2[1]; o[nt][3] *= alpha2[1];
        }

        __syncwarp();

#pragma unroll
        for (int kk = 0; kk < ABN/16; kk++) {
            uint32_t ah[4], al[4];
            {
                int rb  = (wid*16 + g)*SP_ST + kk*16;
                int rb8 = rb + 8*SP_ST;
                float2 x0 = *(const float2*)&sp[rb  + 2*t4];
                float2 x1 = *(const float2*)&sp[rb8 + 2*t4];
                float2 x2 = *(const float2*)&sp[rb  + 2*t4 + 8];
                float2 x3 = *(const float2*)&sp[rb8 + 2*t4 + 8];
                split_bf16(x0.x, x0.y, ah[0], al[0]);
                split_bf16(x1.x, x1.y, ah[1], al[1]);
                split_bf16(x2.x, x2.y, ah[2], al[2]);
                split_bf16(x3.x, x3.y, ah[3], al[3]);
            }
            const int kb = kk*16;
#pragma unroll
            for (int nt = 0; nt < 16; nt++) {
                const int col = nt*8 + g;
                float v00 = sv[(kb + 2*t4    )*SV_ST + col];
                float v01 = sv[(kb + 2*t4 + 1)*SV_ST + col];
                float v10 = sv[(kb + 2*t4 + 8)*SV_ST + col];
                float v11 = sv[(kb + 2*t4 + 9)*SV_ST + col];
                uint32_t bh0, bl0, bh1, bl1;
                split_bf16(v00, v01, bh0, bl0);
                split_bf16(v10, v11, bh1, bl1);
                float* c = o[nt];
                mma_bf16(c, ah[0], ah[1], ah[2], ah[3], bh0, bh1);
                mma_bf16(c, ah[0], ah[1], ah[2], ah[3], bl0, bl1);
                mma_bf16(c, al[0], al[1], al[2], al[3], bh0, bh1);
            }
        }
    }

    const float inv0 = 1.f / lrow[0];
    const float inv1 = 1.f / lrow[1];
    const int r0 = qt*ABM + wid*16 + g;
    float* Ag0 = Aout + (size_t)(b*SEQ + r0) * HID + h*HD;
    float* Ag1 = Ag0 + 8*(size_t)HID;
#pragma unroll
    for (int nt = 0; nt < 16; nt++) {
        int col = nt*8 + 2*t4;
        *(float2*)(Ag0 + col) = make_float2(o[nt][0]*inv0, o[nt][1]*inv0);
        *(float2*)(Ag1 + col) = make_float2(o[nt][2]*inv1, o[nt][3]*inv1);
    }
}

// ---------------------------------------------------------------------------
// Launch.
// ---------------------------------------------------------------------------
extern "C" void kernel_launch(void* const* d_in, const int* in_sizes, int n_in,
                              void* d_out, int out_size)
{
    const void* slot[12];
    if (n_in >= 12 && in_sizes[0] == (int)(TOK*(size_t)HID)) {
        for (int i = 0; i < 12; i++) slot[i] = d_in[i];
    } else {
        // alphabetical: cos,k_b,k_w,kv_buffer,o_w,q_b,q_w,select_index,sin,v_b,v_w,x
        slot[8]  = d_in[0];
        slot[4]  = d_in[1];
        slot[3]  = d_in[2];
        slot[10] = d_in[3];
        slot[7]  = d_in[4];
        slot[2]  = d_in[5];
        slot[1]  = d_in[6];
        slot[11] = d_in[7];
        slot[9]  = d_in[8];
        slot[6]  = d_in[9];
        slot[5]  = d_in[10];
        slot[0]  = d_in[11];
    }

    const float* x     = (const float*)slot[0];
    const float* q_w   = (const float*)slot[1];
    const float* q_b   = (const float*)slot[2];
    const float* k_w   = (const float*)slot[3];
    const float* k_b   = (const float*)slot[4];
    const float* v_w   = (const float*)slot[5];
    const float* v_b   = (const float*)slot[6];
    const float* o_w   = (const float*)slot[7];
    const float* cosb  = (const float*)slot[8];
    const float* sinb  = (const float*)slot[9];
    const float* kvbuf = (const float*)slot[10];
    const void*  sel   = slot[11];

    float* out = (float*)d_out;
    bool has_buf = (size_t)out_size >= OUT_ELEMS + BUF_ELEMS;
    float* buf_out = out + ((size_t)out_size - BUF_ELEMS);

    float *Q, *K, *V, *A;
    uint32_t *xs, *qws, *kws, *vws, *ows, *As;
    cudaGetSymbolAddress((void**)&Q, g_Q);
    cudaGetSymbolAddress((void**)&K, g_K);
    cudaGetSymbolAddress((void**)&V, g_V);
    cudaGetSymbolAddress((void**)&A, g_A);
    cudaGetSymbolAddress((void**)&xs, g_xs);
    cudaGetSymbolAddress((void**)&qws, g_qws);
    cudaGetSymbolAddress((void**)&kws, g_kws);
    cudaGetSymbolAddress((void**)&vws, g_vws);
    cudaGetSymbolAddress((void**)&ows, g_ows);
    cudaGetSymbolAddress((void**)&As, g_As);

    // Pre-split inputs (x, weights) into packed bf16 hi/lo
    presplit_kernel<<<(TOK*HID/8 + 255)/256, 256>>>(x, xs, TOK*HID/8);
    presplit_kernel<<<(HID*HID/8 + 255)/256, 256>>>(q_w, qws, HID*HID/8);
    presplit_kernel<<<(KVDIM*HID/8 + 255)/256, 256>>>(k_w, kws, KVDIM*HID/8);
    presplit_kernel<<<(KVDIM*HID/8 + 255)/256, 256>>>(v_w, vws, KVDIM*HID/8);
    presplit_kernel<<<(HID*HID/8 + 255)/256, 256>>>(o_w, ows, HID*HID/8);

    // Q projection
    gemm_ps_kernel<<<dim3(HID/128, TOK/128, 1), 256>>>(
        xs, qws, q_b, Q, qws, q_b, Q, HID);
    // K + V projections fused (z selects operand set)
    gemm_ps_kernel<<<dim3(KVDIM/128, TOK/128, 2), 256>>>(
        xs, kws, k_b, K, vws, v_b, V, KVDIM);

    // RoPE on Q and K (in place)
    rope_kernel<<<dim3(TOK, NHEAD + NKV), 64>>>(Q, K, cosb, sinb);

    // KV buffer output
    if (has_buf) {
        cudaMemcpyAsync(buf_out, kvbuf, BUF_ELEMS * sizeof(float),
                        cudaMemcpyDeviceToDevice);
        scatter_kernel<<<TOK, 128>>>(K, V, sel, buf_out);
    }

    // Attention (R10 kernel)
    cudaFuncSetAttribute(attn_mma_kernel,
                         cudaFuncAttributeMaxDynamicSharedMemorySize,
                         (int)ATTN_SMEM);
    attn_mma_kernel<<<dim3(SEQ/ABM, BATCH*NHEAD), 256, ATTN_SMEM>>>(Q, K, V, A);

    // Pre-split attention output, then O projection
    presplit_kernel<<<(TOK*HID/8 + 255)/256, 256>>>(A, As, TOK*HID/8);
    gemm_ps_kernel<<<dim3(HID/128, TOK/128, 1), 256>>>(
        As, ows, nullptr, out, ows, nullptr, out, HID);
}

// round 13
// speedup vs baseline: 1.3235x; 1.0426x over previous
#include <cuda_runtime.h>
#include <cuda_bf16.h>
#include <cstdint>

// Problem constants
#define BATCH 4
#define SEQ   1024
#define HID   2048
#define NHEAD 16
#define NKV   2
#define HD    128
#define TOK   (BATCH*SEQ)          // 4096
#define KVDIM (NKV*HD)             // 256
#define OUT_ELEMS ((size_t)TOK*HID)
#define BUF_ELEMS ((size_t)2*TOK*2*NKV*HD)

// Scratch (device globals — no allocation allowed)
__device__ float g_Q[TOK*HID];
__device__ float g_K[TOK*KVDIM];
__device__ float g_V[TOK*KVDIM];
__device__ float g_A[TOK*HID];
// pre-split (packed bf16 hi|lo) operands
__device__ uint32_t g_xs[TOK*HID];
__device__ uint32_t g_qws[HID*HID];
__device__ uint32_t g_kws[KVDIM*HID];
__device__ uint32_t g_vws[KVDIM*HID];
__device__ uint32_t g_ows[HID*HID];
__device__ uint32_t g_As[TOK*HID];
// pre-split attention operands
__device__ uint32_t g_Qs[TOK*HID];
__device__ uint32_t g_Ks[TOK*KVDIM];
__device__ uint32_t g_Vt[(size_t)BATCH*NKV*HD*SEQ];   // [b,kvh][d][key-words]

// ---------------------------------------------------------------------------
// bf16 split helpers
// ---------------------------------------------------------------------------
__device__ __forceinline__ void split_bf16(float x0, float x1,
                                           uint32_t& hi, uint32_t& lo)
{
    asm("cvt.rn.bf16x2.f32 %0, %1, %2;" : "=r"(hi) : "f"(x1), "f"(x0));
    float h0 = __uint_as_float(hi << 16);
    float h1 = __uint_as_float(hi & 0xffff0000u);
    asm("cvt.rn.bf16x2.f32 %0, %1, %2;" : "=r"(lo) : "f"(x1 - h1), "f"(x0 - h0));
}

__device__ __forceinline__ void mma_bf16(float c[4],
    uint32_t a0, uint32_t a1, uint32_t a2, uint32_t a3,
    uint32_t b0, uint32_t b1)
{
    asm volatile(
        "mma.sync.aligned.m16n8k16.row.col.f32.bf16.bf16.f32 "
        "{%0,%1,%2,%3}, {%4,%5,%6,%7}, {%8,%9}, {%0,%1,%2,%3};"
        : "+f"(c[0]), "+f"(c[1]), "+f"(c[2]), "+f"(c[3])
        : "r"(a0), "r"(a1), "r"(a2), "r"(a3), "r"(b0), "r"(b1));
}

__device__ __forceinline__ void cpa16(uint32_t smem_addr, const void* gptr) {
    asm volatile("cp.async.ca.shared.global [%0], [%1], 16;\n"
                 :: "r"(smem_addr), "l"(gptr));
}

// ---------------------------------------------------------------------------
// Pre-split kernel: fp32 -> packed hi/lo, per k16 group: [hi p0..p7][lo p0..p7]
// ---------------------------------------------------------------------------
__global__ void presplit_kernel(const float* __restrict__ src,
                                uint32_t* __restrict__ dst, int n8)
{
    int idx = blockIdx.x * blockDim.x + threadIdx.x;
    if (idx >= n8) return;
    const float4 v0 = *(const float4*)(src + (size_t)idx*8);
    const float4 v1 = *(const float4*)(src + (size_t)idx*8 + 4);
    uint4 h, l;
    split_bf16(v0.x, v0.y, h.x, l.x);
    split_bf16(v0.z, v0.w, h.y, l.y);
    split_bf16(v1.x, v1.y, h.z, l.z);
    split_bf16(v1.z, v1.w, h.w, l.w);
    size_t base = (size_t)(idx >> 1)*16 + (idx & 1)*4;
    *(uint4*)(dst + base)     = h;
    *(uint4*)(dst + base + 8) = l;
}

// ---------------------------------------------------------------------------
// GEMM-NT on pre-split operands (R12, unchanged).
// ---------------------------------------------------------------------------
#define GST 24
#define NK_TILES (HID/16)

__global__ __launch_bounds__(256) void gemm_ps_kernel(
    const uint32_t* __restrict__ A,
    const uint32_t* __restrict__ B0, const float* __restrict__ bias0,
    float* __restrict__ C0,
    const uint32_t* __restrict__ B1, const float* __restrict__ bias1,
    float* __restrict__ C1,
    int N)
{
    __shared__ __align__(16) uint32_t As[2][128*GST];
    __shared__ __align__(16) uint32_t Bs[2][128*GST];

    const uint32_t* B   = blockIdx.z ? B1   : B0;
    const float*    bias= blockIdx.z ? bias1: bias0;
    float*          C   = blockIdx.z ? C1   : C0;

    const int tid  = threadIdx.x;
    const int lane = tid & 31;
    const int wid  = tid >> 5;
    const int g    = lane >> 2;
    const int t4   = lane & 3;
    const int wm   = wid >> 2;
    const int wn   = wid & 3;

    const int m0 = blockIdx.y * 128;
    const int n0 = blockIdx.x * 128;
    const int K  = HID;

    const int ch0 = tid, ch1 = tid + 256;
    const int r0c = ch0 >> 2, q0c = (ch0 & 3)*4;
    const int r1c = ch1 >> 2, q1c = (ch1 & 3)*4;

    float acc[16][4];
#pragma unroll
    for (int i = 0; i < 16; i++)
#pragma unroll
        for (int j = 0; j < 4; j++) acc[i][j] = 0.f;

    auto issue = [&](int s, int gi) {
        const uint32_t* Ag = A + (size_t)(m0 + r0c)*K + gi*16 + q0c;
        const uint32_t* Bg = B + (size_t)(n0 + r0c)*K + gi*16 + q0c;
        cpa16((uint32_t)__cvta_generic_to_shared(&As[s][r0c*GST + q0c]), Ag);
        cpa16((uint32_t)__cvta_generic_to_shared(&Bs[s][r0c*GST + q0c]), Bg);
        const uint32_t* Ag1 = A + (size_t)(m0 + r1c)*K + gi*16 + q1c;
        const uint32_t* Bg1 = B + (size_t)(n0 + r1c)*K + gi*16 + q1c;
        cpa16((uint32_t)__cvta_generic_to_shared(&As[s][r1c*GST + q1c]), Ag1);
        cpa16((uint32_t)__cvta_generic_to_shared(&Bs[s][r1c*GST + q1c]), Bg1);
        asm volatile("cp.async.commit_group;\n" ::: "memory");
    };

    issue(0, 0);

    for (int it = 0; it < NK_TILES; it++) {
        const int cur = it & 1;
        if (it + 1 < NK_TILES) {
            issue(cur ^ 1, it + 1);
            asm volatile("cp.async.wait_group 1;\n" ::: "memory");
        } else {
            asm volatile("cp.async.wait_group 0;\n" ::: "memory");
        }
        __syncthreads();

        const uint32_t* Asc = As[cur];
        const uint32_t* Bsc = Bs[cur];

        uint2 tah[4][2], tal[4][2];
#pragma unroll
        for (int mt = 0; mt < 4; mt++) {
            const uint32_t* ar = Asc + (wm*64 + mt*16 + g)*GST;
            tah[mt][0] = *(const uint2*)(ar + 2*t4);
            tah[mt][1] = *(const uint2*)(ar + 8*GST + 2*t4);
            tal[mt][0] = *(const uint2*)(ar + 8 + 2*t4);
            tal[mt][1] = *(const uint2*)(ar + 8*GST + 8 + 2*t4);
        }
#pragma unroll
        for (int nt = 0; nt < 4; nt++) {
            const uint32_t* br = Bsc + (wn*32 + nt*8 + g)*GST;
            uint2 bh = *(const uint2*)(br + 2*t4);
            uint2 bl = *(const uint2*)(br + 8 + 2*t4);
#pragma unroll
            for (int mt = 0; mt < 4; mt++) {
                float* c = acc[mt*4 + nt];
                mma_bf16(c, tah[mt][0].x, tah[mt][1].x, tah[mt][0].y, tah[mt][1].y, bh.x, bh.y);
                mma_bf16(c, tah[mt][0].x, tah[mt][1].x, tah[mt][0].y, tah[mt][1].y, bl.x, bl.y);
                mma_bf16(c, tal[mt][0].x, tal[mt][1].x, tal[mt][0].y, tal[mt][1].y, bh.x, bh.y);
            }
        }
        __syncthreads();
    }

#pragma unroll
    for (int mt = 0; mt < 4; mt++) {
#pragma unroll
        for (int nt = 0; nt < 4; nt++) {
            const float* c = acc[mt*4 + nt];
            int row0 = m0 + wm*64 + mt*16 + g;
            int col  = n0 + wn*32 + nt*8 + 2*t4;
            float b0 = bias ? bias[col]     : 0.f;
            float b1 = bias ? bias[col + 1] : 0.f;
            float2 v0 = make_float2(c[0] + b0, c[1] + b1);
            float2 v1 = make_float2(c[2] + b0, c[3] + b1);
            *(float2*)(C + (size_t)row0 * N + col)       = v0;
            *(float2*)(C + (size_t)(row0 + 8) * N + col) = v1;
        }
    }
}

// ---------------------------------------------------------------------------
// RoPE + pre-split: reads fp32 Q/K, writes packed hi/lo Qs/Ks.
// K additionally written back fp32 (scatter needs roped K).
// Thread j handles floats (2j, 2j+1) of one head slice. Partner floats are
// owned by thread j+-32 -> sync between load and store.
// ---------------------------------------------------------------------------
__global__ void rope_split_kernel(const float* __restrict__ Q,
                                  float* __restrict__ K,
                                  const float* __restrict__ cosb,
                                  const float* __restrict__ sinb,
                                  uint32_t* __restrict__ Qs,
                                  uint32_t* __restrict__ Ks)
{
    int t  = blockIdx.x;
    int hy = blockIdx.y;
    int j  = threadIdx.x;          // 0..63
    int s  = t & (SEQ - 1);
    int f0 = 2*j;
    float c0 = cosb[s*HD + f0],     c1 = cosb[s*HD + f0 + 1];
    float s0 = sinb[s*HD + f0],     s1 = sinb[s*HD + f0 + 1];

    const float* src;
    float* wb = nullptr;
    uint32_t* dst;
    if (hy < NHEAD) {
        src = Q + (size_t)t*HID + hy*HD;
        dst = Qs + (size_t)t*HID + hy*HD;
    } else {
        float* kp = K + (size_t)t*KVDIM + (hy - NHEAD)*HD;
        src = kp; wb = kp;
        dst = Ks + (size_t)t*KVDIM + (hy - NHEAD)*HD;
    }

    float xa = src[f0], xb = src[f0 + 1];
    int pf = (j < 32) ? f0 + 64 : f0 - 64;
    float pa = src[pf], pb = src[pf + 1];
    __syncthreads();   // all reads done before fp32 write-back

    float r0 = (j < 32) ? -pa : pa;
    float r1 = (j < 32) ? -pb : pb;
    float o0 = xa*c0 + r0*s0;
    float o1 = xb*c1 + r1*s1;

    uint32_t h, l;
    split_bf16(o0, o1, h, l);
    int w = (j >> 3)*16 + (j & 7);
    dst[w]     = h;
    dst[w + 8] = l;
    if (wb) { wb[f0] = o0; wb[f0 + 1] = o1; }
}

// ---------------------------------------------------------------------------
// V transpose + pre-split: V[token][kvh*128+d] -> Vt[(b,kvh)][d][key-words],
// words grouped per 16 keys as [hi p0..p7][lo p0..p7].
// grid (SEQ/64, BATCH*NKV), 256 threads.
// ---------------------------------------------------------------------------
__global__ __launch_bounds__(256) void vt_kernel(const float* __restrict__ V,
                                                 uint32_t* __restrict__ Vt)
{
    __shared__ float ts[64*133];
    const int kc  = blockIdx.x;
    const int bh2 = blockIdx.y;
    const int b   = bh2 >> 1;
    const int kvh = bh2 & 1;
    const int tid = threadIdx.x;

    for (int i = tid; i < 64*32; i += 256) {
        int r = i >> 5, c4 = i & 31;
        float4 v = *(const float4*)(V + (size_t)(b*SEQ + kc*64 + r)*KVDIM
                                      + kvh*HD + c4*4);
        float* d = ts + r*133 + c4*4;
        d[0] = v.x; d[1] = v.y; d[2] = v.z; d[3] = v.w;
    }
    __syncthreads();

    uint32_t* out = Vt + (size_t)bh2*HD*SEQ + kc*64;
    for (int i = tid; i < 128*32; i += 256) {
        int d = i >> 5, l = i & 31;
        int w0 = 2*l;
        uint2 o;
        {
            int w = w0, gi = w >> 4, ss = w & 15, p = ss & 7;
            int lk = gi*16 + 2*p;
            uint32_t h, lo;
            split_bf16(ts[lk*133 + d], ts[(lk+1)*133 + d], h, lo);
            o.x = (ss < 8) ? h : lo;
        }
        {
            int w = w0 + 1, gi = w >> 4, ss = w & 15, p = ss & 7;
            int lk = gi*16 + 2*p;
            uint32_t h, lo;
            split_bf16(ts[lk*133 + d], ts[(lk+1)*133 + d], h, lo);
            o.y = (ss < 8) ? h : lo;
        }
        *(uint2*)(out + (size_t)d*SEQ + w0) = o;
    }
}

// ---------------------------------------------------------------------------
// Scatter K/V into output kv buffer (dtype-sniffing select_index).
// ---------------------------------------------------------------------------
__global__ void scatter_kernel(const float* __restrict__ K,
                               const float* __restrict__ V,
                               const void* __restrict__ idx,
                               float* __restrict__ buf)
{
    int t = blockIdx.x;
    int d = threadIdx.x;
    const long long* i64 = (const long long*)idx;
    const int*       i32 = (const int*)idx;
    bool is64 = ((unsigned long long)i64[1]) < (unsigned long long)(2*TOK);
    long long row = is64 ? i64[t] : (long long)i32[t];
    if (row < 0 || row >= (long long)(2*TOK)) return;
    size_t base = (size_t)row * 4 * HD;
    buf[base + 0*HD + d] = K[(size_t)t*KVDIM + d];
    buf[base + 1*HD + d] = K[(size_t)t*KVDIM + HD + d];
    buf[base + 2*HD + d] = V[(size_t)t*KVDIM + d];
    buf[base + 3*HD + d] = V[(size_t)t*KVDIM + HD + d];
}

// ---------------------------------------------------------------------------
// Tensor-core flash attention on PRE-SPLIT operands.
// sq/sk rows: packed hi/lo words (stride 136); sv: d-major key-words (72);
// sp: P pre-split at write (72). Zero Q/K/V splits in hot loop.
// ---------------------------------------------------------------------------
#define ABM 128
#define ABN 64
#define SQ2 136
#define SK2 136
#define SV2 72
#define SP2 72
#define ATTN_SMEM ((ABM*SQ2 + ABN*SK2 + ABM*SV2 + ABM*SP2) * sizeof(uint32_t))

__global__ __launch_bounds__(256, 1) void attn_ps_kernel(
    const uint32_t* __restrict__ Qs, const uint32_t* __restrict__ Ks,
    const uint32_t* __restrict__ Vt, float* __restrict__ Aout)
{
    extern __shared__ __align__(16) uint32_t smu[];
    uint32_t* sq = smu;                 // 128 x 136
    uint32_t* sk = sq + ABM*SQ2;        // 64 x 136
    uint32_t* sv = sk + ABN*SK2;        // 128 x 72 (rows = d)
    uint32_t* sp = sv + ABM*SV2;        // 128 x 72

    const int bh  = blockIdx.y;
    const int b   = bh / NHEAD;
    const int h   = bh % NHEAD;
    const int kvh = h / (NHEAD / NKV);
    const int qt  = blockIdx.x;
    const int tid = threadIdx.x;
    const int lane = tid & 31;
    const int wid  = tid >> 5;
    const int g    = lane >> 2;
    const int t4   = lane & 3;
    const float scale = 0.08838834764831845f;

    // load pre-split Q tile
    const uint32_t* Qg = Qs + (size_t)(b*SEQ + qt*ABM)*HID + h*HD;
    for (int i = tid; i < ABM*32; i += 256) {
        int r = i >> 5, c4 = i & 31;
        *(uint4*)(sq + r*SQ2 + c4*4) = *(const uint4*)(Qg + (size_t)r*HID + c4*4);
    }

    float o[16][4];
#pragma unroll
    for (int i = 0; i < 16; i++)
#pragma unroll
        for (int j = 0; j < 4; j++) o[i][j] = 0.f;
    float mrow[2] = {-1e30f, -1e30f};
    float lrow[2] = {0.f, 0.f};

    const int qrow_base = qt*ABM + wid*16;
    const int nkt = 2*qt + 2;
    const uint32_t* Vg = Vt + (size_t)(b*NKV + kvh)*HD*SEQ;

    for (int kt = 0; kt < nkt; kt++) {
        __syncthreads();
        // cp.async K tile (64 rows x 32 uint4)
        for (int i = tid; i < ABN*32; i += 256) {
            int r = i >> 5, c4 = i & 31;
            cpa16((uint32_t)__cvta_generic_to_shared(sk + r*SK2 + c4*4),
                  Ks + (size_t)(b*SEQ + kt*ABN + r)*KVDIM + kvh*HD + c4*4);
        }
        // cp.async V tile (128 d-rows x 16 uint4)
        for (int i = tid; i < ABM*16; i += 256) {
            int r = i >> 4, c4 = i & 15;
            cpa16((uint32_t)__cvta_generic_to_shared(sv + r*SV2 + c4*4),
                  Vg + (size_t)r*SEQ + kt*ABN + c4*4);
        }
        asm volatile("cp.async.commit_group;\n" ::: "memory");
        asm volatile("cp.async.wait_group 0;\n" ::: "memory");
        __syncthreads();

        const int kcol_base = kt*ABN;
        if (kcol_base > qrow_base + 15) continue;

        // ---- S = Q K^T ----
        float sacc[8][4];
#pragma unroll
        for (int i = 0; i < 8; i++)
#pragma unroll
            for (int j = 0; j < 4; j++) sacc[i][j] = 0.f;

#pragma unroll
        for (int kk = 0; kk < HD/16; kk++) {
            const uint32_t* qr = sq + (wid*16 + g)*SQ2 + kk*16 + 2*t4;
            uint2 ah02 = *(const uint2*)(qr);
            uint2 ah13 = *(const uint2*)(qr + 8*SQ2);
            uint2 al02 = *(const uint2*)(qr + 8);
            uint2 al13 = *(const uint2*)(qr + 8*SQ2 + 8);
#pragma unroll
            for (int nt = 0; nt < 8; nt++) {
                const uint32_t* kr = sk + (nt*8 + g)*SK2 + kk*16 + 2*t4;
                uint2 bhv = *(const uint2*)(kr);
                uint2 blv = *(const uint2*)(kr + 8);
                float* c = sacc[nt];
                mma_bf16(c, ah02.x, ah13.x, ah02.y, ah13.y, bhv.x, bhv.y);
                mma_bf16(c, ah02.x, ah13.x, ah02.y, ah13.y, blv.x, blv.y);
                mma_bf16(c, al02.x, al13.x, al02.y, al13.y, bhv.x, bhv.y);
            }
        }

        // ---- mask + online softmax; P pre-split at write ----
        const bool need_mask = (kcol_base + ABN - 1) > qrow_base;
        float alpha2[2];
#pragma unroll
        for (int hh = 0; hh < 2; hh++) {
            const int qg = qrow_base + g + 8*hh;
            float mx = -1e30f;
#pragma unroll
            for (int nt = 0; nt < 8; nt++) {
#pragma unroll
                for (int j = 0; j < 2; j++) {
                    float s = sacc[nt][2*hh + j] * scale;
                    if (need_mask) {
                        int kg = kcol_base + nt*8 + 2*t4 + j;
                        if (kg > qg) s = -1e30f;
                    }
                    sacc[nt][2*hh + j] = s;
                    mx = fmaxf(mx, s);
                }
            }
            mx = fmaxf(mx, __shfl_xor_sync(0xffffffffu, mx, 1));
            mx = fmaxf(mx, __shfl_xor_sync(0xffffffffu, mx, 2));
            float mnew = fmaxf(mrow[hh], mx);
            float alpha = __expf(mrow[hh] - mnew);
            float sum = 0.f;
            const int prow = (wid*16 + g + 8*hh)*SP2;
#pragma unroll
            for (int nt = 0; nt < 8; nt++) {
                float p0 = __expf(sacc[nt][2*hh]     - mnew);
                float p1 = __expf(sacc[nt][2*hh + 1] - mnew);
                uint32_t hv, lv;
                split_bf16(p0, p1, hv, lv);
                int kp = nt*4 + t4;
                int cph = (kp >> 3)*16 + (kp & 7);
                sp[prow + cph]     = hv;
                sp[prow + cph + 8] = lv;
                sum += p0 + p1;
            }
            sum += __shfl_xor_sync(0xffffffffu, sum, 1);
            sum += __shfl_xor_sync(0xffffffffu, sum, 2);
            lrow[hh] = lrow[hh]*alpha + sum;
            mrow[hh] = mnew;
            alpha2[hh] = alpha;
        }

#pragma unroll
        for (int nt = 0; nt < 16; nt++) {
            o[nt][0] *= alpha2[0]; o[nt][1] *= alpha2[0];
            o[nt][2] *= alpha2[1]; o[nt][3] *= alpha2[1];
        }

        __syncwarp();   // sp is warp-private

        // ---- O += P V ----
#pragma unroll
        for (int kk = 0; kk < ABN/16; kk++) {
            const uint32_t* pr = sp + (wid*16 + g)*SP2 + kk*16 + 2*t4;
            uint2 ah02 = *(const uint2*)(pr);
            uint2 ah13 = *(const uint2*)(pr + 8*SP2);
            uint2 al02 = *(const uint2*)(pr + 8);
            uint2 al13 = *(const uint2*)(pr + 8*SP2 + 8);
#pragma unroll
            for (int nt = 0; nt < 16; nt++) {
                const uint32_t* vr = sv + (nt*8 + g)*SV2 + kk*16 + 2*t4;
                uint2 bhv = *(const uint2*)(vr);
                uint2 blv = *(const uint2*)(vr + 8);
                float* c = o[nt];
                mma_bf16(c, ah02.x, ah13.x, ah02.y, ah13.y, bhv.x, bhv.y);
                mma_bf16(c, ah02.x, ah13.x, ah02.y, ah13.y, blv.x, blv.y);
                mma_bf16(c, al02.x, al13.x, al02.y, al13.y, bhv.x, bhv.y);
            }
        }
    }

    // epilogue
    const float inv0 = 1.f / lrow[0];
    const float inv1 = 1.f / lrow[1];
    const int r0 = qt*ABM + wid*16 + g;
    float* Ag0 = Aout + (size_t)(b*SEQ + r0) * HID + h*HD;
    float* Ag1 = Ag0 + 8*(size_t)HID;
#pragma unroll
    for (int nt = 0; nt < 16; nt++) {
        int col = nt*8 + 2*t4;
        *(float2*)(Ag0 + col) = make_float2(o[nt][0]*inv0, o[nt][1]*inv0);
        *(float2*)(Ag1 + col) = make_float2(o[nt][2]*inv1, o[nt][3]*inv1);
    }
}

// ---------------------------------------------------------------------------
// Launch.
// ---------------------------------------------------------------------------
extern "C" void kernel_launch(void* const* d_in, const int* in_sizes, int n_in,
                              void* d_out, int out_size)
{
    const void* slot[12];
    if (n_in >= 12 && in_sizes[0] == (int)(TOK*(size_t)HID)) {
        for (int i = 0; i < 12; i++) slot[i] = d_in[i];
    } else {
        // alphabetical: cos,k_b,k_w,kv_buffer,o_w,q_b,q_w,select_index,sin,v_b,v_w,x
        slot[8]  = d_in[0];
        slot[4]  = d_in[1];
        slot[3]  = d_in[2];
        slot[10] = d_in[3];
        slot[7]  = d_in[4];
        slot[2]  = d_in[5];
        slot[1]  = d_in[6];
        slot[11] = d_in[7];
        slot[9]  = d_in[8];
        slot[6]  = d_in[9];
        slot[5]  = d_in[10];
        slot[0]  = d_in[11];
    }

    const float* x     = (const float*)slot[0];
    const float* q_w   = (const float*)slot[1];
    const float* q_b   = (const float*)slot[2];
    const float* k_w   = (const float*)slot[3];
    const float* k_b   = (const float*)slot[4];
    const float* v_w   = (const float*)slot[5];
    const float* v_b   = (const float*)slot[6];
    const float* o_w   = (const float*)slot[7];
    const float* cosb  = (const float*)slot[8];
    const float* sinb  = (const float*)slot[9];
    const float* kvbuf = (const float*)slot[10];
    const void*  sel   = slot[11];

    float* out = (float*)d_out;
    bool has_buf = (size_t)out_size >= OUT_ELEMS + BUF_ELEMS;
    float* buf_out = out + ((size_t)out_size - BUF_ELEMS);

    float *Q, *K, *V, *A;
    uint32_t *xs, *qws, *kws, *vws, *ows, *As, *Qsp, *Ksp, *Vtp;
    cudaGetSymbolAddress((void**)&Q, g_Q);
    cudaGetSymbolAddress((void**)&K, g_K);
    cudaGetSymbolAddress((void**)&V, g_V);
    cudaGetSymbolAddress((void**)&A, g_A);
    cudaGetSymbolAddress((void**)&xs, g_xs);
    cudaGetSymbolAddress((void**)&qws, g_qws);
    cudaGetSymbolAddress((void**)&kws, g_kws);
    cudaGetSymbolAddress((void**)&vws, g_vws);
    cudaGetSymbolAddress((void**)&ows, g_ows);
    cudaGetSymbolAddress((void**)&As, g_As);
    cudaGetSymbolAddress((void**)&Qsp, g_Qs);
    cudaGetSymbolAddress((void**)&Ksp, g_Ks);
    cudaGetSymbolAddress((void**)&Vtp, g_Vt);

    // Pre-split inputs
    presplit_kernel<<<(TOK*HID/8 + 255)/256, 256>>>(x, xs, TOK*HID/8);
    presplit_kernel<<<(HID*HID/8 + 255)/256, 256>>>(q_w, qws, HID*HID/8);
    presplit_kernel<<<(KVDIM*HID/8 + 255)/256, 256>>>(k_w, kws, KVDIM*HID/8);
    presplit_kernel<<<(KVDIM*HID/8 + 255)/256, 256>>>(v_w, vws, KVDIM*HID/8);
    presplit_kernel<<<(HID*HID/8 + 255)/256, 256>>>(o_w, ows, HID*HID/8);

    // Projections
    gemm_ps_kernel<<<dim3(HID/128, TOK/128, 1), 256>>>(
        xs, qws, q_b, Q, qws, q_b, Q, HID);
    gemm_ps_kernel<<<dim3(KVDIM/128, TOK/128, 2), 256>>>(
        xs, kws, k_b, K, vws, v_b, V, KVDIM);

    // RoPE + pre-split Q/K; V transpose + pre-split
    rope_split_kernel<<<dim3(TOK, NHEAD + NKV), 64>>>(Q, K, cosb, sinb, Qsp, Ksp);
    vt_kernel<<<dim3(SEQ/64, BATCH*NKV), 256>>>(V, Vtp);

    // KV buffer output (reads roped fp32 K, fp32 V)
    if (has_buf) {
        cudaMemcpyAsync(buf_out, kvbuf, BUF_ELEMS * sizeof(float),
                        cudaMemcpyDeviceToDevice);
        scatter_kernel<<<TOK, 128>>>(K, V, sel, buf_out);
    }

    // Attention on pre-split operands
    cudaFuncSetAttribute(attn_ps_kernel,
                         cudaFuncAttributeMaxDynamicSharedMemorySize,
                         (int)ATTN_SMEM);
    attn_ps_kernel<<<dim3(SEQ/ABM, BATCH*NHEAD), 256, ATTN_SMEM>>>(Qsp, Ksp, Vtp, A);

    // O projection
    presplit_kernel<<<(TOK*HID/8 + 255)/256, 256>>>(A, As, TOK*HID/8);
    gemm_ps_kernel<<<dim3(HID/128, TOK/128, 1), 256>>>(
        As, ows, nullptr, out, ows, nullptr, out, HID);
}

// round 15
// speedup vs baseline: 1.4413x; 1.0890x over previous
#include <cuda_runtime.h>
#include <cuda_bf16.h>
#include <cstdint>

// Problem constants
#define BATCH 4
#define SEQ   1024
#define HID   2048
#define NHEAD 16
#define NKV   2
#define HD    128
#define TOK   (BATCH*SEQ)          // 4096
#define KVDIM (NKV*HD)             // 256
#define OUT_ELEMS ((size_t)TOK*HID)
#define BUF_ELEMS ((size_t)2*TOK*2*NKV*HD)

// Scratch (device globals — no allocation allowed)
__device__ float g_Q[TOK*HID];
__device__ float g_K[TOK*KVDIM];
__device__ float g_V[TOK*KVDIM];
// pre-split (packed bf16 hi|lo) operands, flat format:
// per row, per 16-float k-group: [hi p0..p7][lo p0..p7] (16 u32)
__device__ uint32_t g_xs[TOK*HID];
__device__ uint32_t g_qws[HID*HID];
__device__ uint32_t g_kws[KVDIM*HID];
__device__ uint32_t g_vws[KVDIM*HID];
__device__ uint32_t g_ows[HID*HID];
__device__ uint32_t g_As[TOK*HID];      // attention output, written pre-split
// pre-split attention operands
__device__ uint32_t g_Qs[TOK*HID];
__device__ uint32_t g_Ks[TOK*KVDIM];
__device__ uint32_t g_Vt[(size_t)BATCH*NKV*HD*SEQ];

// ---------------------------------------------------------------------------
// bf16 split helpers
// ---------------------------------------------------------------------------
__device__ __forceinline__ void split_bf16(float x0, float x1,
                                           uint32_t& hi, uint32_t& lo)
{
    asm("cvt.rn.bf16x2.f32 %0, %1, %2;" : "=r"(hi) : "f"(x1), "f"(x0));
    float h0 = __uint_as_float(hi << 16);
    float h1 = __uint_as_float(hi & 0xffff0000u);
    asm("cvt.rn.bf16x2.f32 %0, %1, %2;" : "=r"(lo) : "f"(x1 - h1), "f"(x0 - h0));
}

__device__ __forceinline__ void mma_bf16(float c[4],
    uint32_t a0, uint32_t a1, uint32_t a2, uint32_t a3,
    uint32_t b0, uint32_t b1)
{
    asm volatile(
        "mma.sync.aligned.m16n8k16.row.col.f32.bf16.bf16.f32 "
        "{%0,%1,%2,%3}, {%4,%5,%6,%7}, {%8,%9}, {%0,%1,%2,%3};"
        : "+f"(c[0]), "+f"(c[1]), "+f"(c[2]), "+f"(c[3])
        : "r"(a0), "r"(a1), "r"(a2), "r"(a3), "r"(b0), "r"(b1));
}

__device__ __forceinline__ void cpa16(uint32_t smem_addr, const void* gptr) {
    asm volatile("cp.async.ca.shared.global [%0], [%1], 16;\n"
                 :: "r"(smem_addr), "l"(gptr));
}

// ---------------------------------------------------------------------------
// Pre-split kernel: fp32 -> packed hi/lo flat layout.
// ---------------------------------------------------------------------------
__global__ void presplit_kernel(const float* __restrict__ src,
                                uint32_t* __restrict__ dst, int n8)
{
    int idx = blockIdx.x * blockDim.x + threadIdx.x;
    if (idx >= n8) return;
    const float4 v0 = *(const float4*)(src + (size_t)idx*8);
    const float4 v1 = *(const float4*)(src + (size_t)idx*8 + 4);
    uint4 h, l;
    split_bf16(v0.x, v0.y, h.x, l.x);
    split_bf16(v0.z, v0.w, h.y, l.y);
    split_bf16(v1.x, v1.y, h.z, l.z);
    split_bf16(v1.z, v1.w, h.w, l.w);
    size_t base = (size_t)(idx >> 1)*16 + (idx & 1)*4;
    *(uint4*)(dst + base)     = h;
    *(uint4*)(dst + base + 8) = l;
}

// ---------------------------------------------------------------------------
// GEMM-NT on pre-split operands, KT=32, 2-stage cp.async, 2 CTAs/SM.
// smem row stride 40 u32: data [g0 hi8 lo8][g1 hi8 lo8] + pad 8.
// Bank check (LDS.64, u64 phase): (20g + t4) mod 16 distinct for g=0..7.
// blockIdx.z selects operand set (fused K/V projection).
// ---------------------------------------------------------------------------
#define GST2 40
#define NK2 (HID/32)    // 64 k-iterations
#define GEMM_SMEM (2*2*128*GST2*4)   // 81920 bytes

__global__ __launch_bounds__(256, 2) void gemm_ps_kernel(
    const uint32_t* __restrict__ A,
    const uint32_t* __restrict__ B0, const float* __restrict__ bias0,
    float* __restrict__ C0,
    const uint32_t* __restrict__ B1, const float* __restrict__ bias1,
    float* __restrict__ C1,
    int N)
{
    extern __shared__ __align__(16) uint32_t dyn[];
    uint32_t* Asm = dyn;                    // [2][128*GST2]
    uint32_t* Bsm = dyn + 2*128*GST2;       // [2][128*GST2]

    const uint32_t* B   = blockIdx.z ? B1   : B0;
    const float*    bias= blockIdx.z ? bias1: bias0;
    float*          C   = blockIdx.z ? C1   : C0;

    const int tid  = threadIdx.x;
    const int lane = tid & 31;
    const int wid  = tid >> 5;
    const int g    = lane >> 2;
    const int t4   = lane & 3;
    const int wm   = wid >> 2;
    const int wn   = wid & 3;

    const int m0 = blockIdx.y * 128;
    const int n0 = blockIdx.x * 128;
    const int K  = HID;

    float acc[16][4];
#pragma unroll
    for (int i = 0; i < 16; i++)
#pragma unroll
        for (int j = 0; j < 4; j++) acc[i][j] = 0.f;

    // copy 128B per row per array per ktile: j in [0,2048): arr, row, q
    auto issue = [&](int s, int it) {
#pragma unroll
        for (int rep = 0; rep < 8; rep++) {
            int j = rep*256 + tid;
            int arr = j >> 10;
            int i = j & 1023;
            int row = i >> 3, q = (i & 7)*4;
            const uint32_t* src = (arr ? (B + (size_t)(n0 + row)*K)
                                       : (A + (size_t)(m0 + row)*K))
                                  + it*32 + q;
            uint32_t* dstb = (arr ? Bsm : Asm) + s*128*GST2 + row*GST2 + q;
            cpa16((uint32_t)__cvta_generic_to_shared(dstb), src);
        }
        asm volatile("cp.async.commit_group;" ::: "memory");
    };

    issue(0, 0);

    for (int it = 0; it < NK2; it++) {
        const int cur = it & 1;
        if (it + 1 < NK2) {
            issue(cur ^ 1, it + 1);
            asm volatile("cp.async.wait_group 1;" ::: "memory");
        } else {
            asm volatile("cp.async.wait_group 0;" ::: "memory");
        }
        __syncthreads();

        const uint32_t* Asc = Asm + cur*128*GST2;
        const uint32_t* Bsc = Bsm + cur*128*GST2;

#pragma unroll
        for (int kg2 = 0; kg2 < 2; kg2++) {
            const int off = kg2*16;
            uint2 tah[4][2], tal[4][2];
#pragma unroll
            for (int mt = 0; mt < 4; mt++) {
                const uint32_t* ar = Asc + (wm*64 + mt*16 + g)*GST2 + off;
                tah[mt][0] = *(const uint2*)(ar + 2*t4);
                tah[mt][1] = *(const uint2*)(ar + 8*GST2 + 2*t4);
                tal[mt][0] = *(const uint2*)(ar + 8 + 2*t4);
                tal[mt][1] = *(const uint2*)(ar + 8*GST2 + 8 + 2*t4);
            }
#pragma unroll
            for (int nt = 0; nt < 4; nt++) {
                const uint32_t* br = Bsc + (wn*32 + nt*8 + g)*GST2 + off;
                uint2 bh = *(const uint2*)(br + 2*t4);
                uint2 bl = *(const uint2*)(br + 8 + 2*t4);
#pragma unroll
                for (int mt = 0; mt < 4; mt++) {
                    float* c = acc[mt*4 + nt];
                    mma_bf16(c, tah[mt][0].x, tah[mt][1].x, tah[mt][0].y, tah[mt][1].y, bh.x, bh.y);
                    mma_bf16(c, tah[mt][0].x, tah[mt][1].x, tah[mt][0].y, tah[mt][1].y, bl.x, bl.y);
                    mma_bf16(c, tal[mt][0].x, tal[mt][1].x, tal[mt][0].y, tal[mt][1].y, bh.x, bh.y);
                }
            }
        }
        __syncthreads();
    }

#pragma unroll
    for (int mt = 0; mt < 4; mt++) {
#pragma unroll
        for (int nt = 0; nt < 4; nt++) {
            const float* c = acc[mt*4 + nt];
            int row0 = m0 + wm*64 + mt*16 + g;
            int col  = n0 + wn*32 + nt*8 + 2*t4;
            float b0 = bias ? bias[col]     : 0.f;
            float b1 = bias ? bias[col + 1] : 0.f;
            float2 v0 = make_float2(c[0] + b0, c[1] + b1);
            float2 v1 = make_float2(c[2] + b0, c[3] + b1);
            *(float2*)(C + (size_t)row0 * N + col)       = v0;
            *(float2*)(C + (size_t)(row0 + 8) * N + col) = v1;
        }
    }
}

// ---------------------------------------------------------------------------
// RoPE + pre-split (R13, unchanged)
// ---------------------------------------------------------------------------
__global__ void rope_split_kernel(const float* __restrict__ Q,
                                  float* __restrict__ K,
                                  const float* __restrict__ cosb,
                                  const float* __restrict__ sinb,
                                  uint32_t* __restrict__ Qs,
                                  uint32_t* __restrict__ Ks)
{
    int t  = blockIdx.x;
    int hy = blockIdx.y;
    int j  = threadIdx.x;
    int s  = t & (SEQ - 1);
    int f0 = 2*j;
    float c0 = cosb[s*HD + f0],     c1 = cosb[s*HD + f0 + 1];
    float s0 = sinb[s*HD + f0],     s1 = sinb[s*HD + f0 + 1];

    const float* src;
    float* wb = nullptr;
    uint32_t* dst;
    if (hy < NHEAD) {
        src = Q + (size_t)t*HID + hy*HD;
        dst = Qs + (size_t)t*HID + hy*HD;
    } else {
        float* kp = K + (size_t)t*KVDIM + (hy - NHEAD)*HD;
        src = kp; wb = kp;
        dst = Ks + (size_t)t*KVDIM + (hy - NHEAD)*HD;
    }

    float xa = src[f0], xb = src[f0 + 1];
    int pf = (j < 32) ? f0 + 64 : f0 - 64;
    float pa = src[pf], pb = src[pf + 1];
    __syncthreads();

    float r0 = (j < 32) ? -pa : pa;
    float r1 = (j < 32) ? -pb : pb;
    float o0 = xa*c0 + r0*s0;
    float o1 = xb*c1 + r1*s1;

    uint32_t h, l;
    split_bf16(o0, o1, h, l);
    int w = (j >> 3)*16 + (j & 7);
    dst[w]     = h;
    dst[w + 8] = l;
    if (wb) { wb[f0] = o0; wb[f0 + 1] = o1; }
}

// ---------------------------------------------------------------------------
// V transpose + pre-split (R13, unchanged)
// ---------------------------------------------------------------------------
__global__ __launch_bounds__(256) void vt_kernel(const float* __restrict__ V,
                                                 uint32_t* __restrict__ Vt)
{
    __shared__ float ts[64*133];
    const int kc  = blockIdx.x;
    const int bh2 = blockIdx.y;
    const int b   = bh2 >> 1;
    const int kvh = bh2 & 1;
    const int tid = threadIdx.x;

    for (int i = tid; i < 64*32; i += 256) {
        int r = i >> 5, c4 = i & 31;
        float4 v = *(const float4*)(V + (size_t)(b*SEQ + kc*64 + r)*KVDIM
                                      + kvh*HD + c4*4);
        float* d = ts + r*133 + c4*4;
        d[0] = v.x; d[1] = v.y; d[2] = v.z; d[3] = v.w;
    }
    __syncthreads();

    uint32_t* out = Vt + (size_t)bh2*HD*SEQ + kc*64;
    for (int i = tid; i < 128*32; i += 256) {
        int d = i >> 5, l = i & 31;
        int w0 = 2*l;
        uint2 o;
        {
            int w = w0, gi = w >> 4, ss = w & 15, p = ss & 7;
            int lk = gi*16 + 2*p;
            uint32_t h, lo;
            split_bf16(ts[lk*133 + d], ts[(lk+1)*133 + d], h, lo);
            o.x = (ss < 8) ? h : lo;
        }
        {
            int w = w0 + 1, gi = w >> 4, ss = w & 15, p = ss & 7;
            int lk = gi*16 + 2*p;
            uint32_t h, lo;
            split_bf16(ts[lk*133 + d], ts[(lk+1)*133 + d], h, lo);
            o.y = (ss < 8) ? h : lo;
        }
        *(uint2*)(out + (size_t)d*SEQ + w0) = o;
    }
}

// ---------------------------------------------------------------------------
// Scatter K/V into output kv buffer (unchanged)
// ---------------------------------------------------------------------------
__global__ void scatter_kernel(const float* __restrict__ K,
                               const float* __restrict__ V,
                               const void* __restrict__ idx,
                               float* __restrict__ buf)
{
    int t = blockIdx.x;
    int d = threadIdx.x;
    const long long* i64 = (const long long*)idx;
    const int*       i32 = (const int*)idx;
    bool is64 = ((unsigned long long)i64[1]) < (unsigned long long)(2*TOK);
    long long row = is64 ? i64[t] : (long long)i32[t];
    if (row < 0 || row >= (long long)(2*TOK)) return;
    size_t base = (size_t)row * 4 * HD;
    buf[base + 0*HD + d] = K[(size_t)t*KVDIM + d];
    buf[base + 1*HD + d] = K[(size_t)t*KVDIM + HD + d];
    buf[base + 2*HD + d] = V[(size_t)t*KVDIM + d];
    buf[base + 3*HD + d] = V[(size_t)t*KVDIM + HD + d];
}

// ---------------------------------------------------------------------------
// Tensor-core flash attention (R13 mainloop); epilogue writes output
// DIRECTLY pre-split into the flat hi/lo format for the O-proj GEMM.
// ---------------------------------------------------------------------------
#define ABM 128
#define ABN 64
#define SQ2 136
#define SK2 136
#define SV2 72
#define SP2 72
#define ATTN_SMEM ((ABM*SQ2 + ABN*SK2 + ABM*SV2 + ABM*SP2) * sizeof(uint32_t))

__global__ __launch_bounds__(256, 1) void attn_ps_kernel(
    const uint32_t* __restrict__ Qs, const uint32_t* __restrict__ Ks,
    const uint32_t* __restrict__ Vt, uint32_t* __restrict__ As_out)
{
    extern __shared__ __align__(16) uint32_t smu[];
    uint32_t* sq = smu;
    uint32_t* sk = sq + ABM*SQ2;
    uint32_t* sv = sk + ABN*SK2;
    uint32_t* sp = sv + ABM*SV2;

    const int bh  = blockIdx.y;
    const int b   = bh / NHEAD;
    const int h   = bh % NHEAD;
    const int kvh = h / (NHEAD / NKV);
    const int qt  = blockIdx.x;
    const int tid = threadIdx.x;
    const int lane = tid & 31;
    const int wid  = tid >> 5;
    const int g    = lane >> 2;
    const int t4   = lane & 3;
    const float scale = 0.08838834764831845f;

    const uint32_t* Qg = Qs + (size_t)(b*SEQ + qt*ABM)*HID + h*HD;
    for (int i = tid; i < ABM*32; i += 256) {
        int r = i >> 5, c4 = i & 31;
        *(uint4*)(sq + r*SQ2 + c4*4) = *(const uint4*)(Qg + (size_t)r*HID + c4*4);
    }

    float o[16][4];
#pragma unroll
    for (int i = 0; i < 16; i++)
#pragma unroll
        for (int j = 0; j < 4; j++) o[i][j] = 0.f;
    float mrow[2] = {-1e30f, -1e30f};
    float lrow[2] = {0.f, 0.f};

    const int qrow_base = qt*ABM + wid*16;
    const int nkt = 2*qt + 2;
    const uint32_t* Vg = Vt + (size_t)(b*NKV + kvh)*HD*SEQ;

    for (int kt = 0; kt < nkt; kt++) {
        __syncthreads();
        for (int i = tid; i < ABN*32; i += 256) {
            int r = i >> 5, c4 = i & 31;
            cpa16((uint32_t)__cvta_generic_to_shared(sk + r*SK2 + c4*4),
                  Ks + (size_t)(b*SEQ + kt*ABN + r)*KVDIM + kvh*HD + c4*4);
        }
        for (int i = tid; i < ABM*16; i += 256) {
            int r = i >> 4, c4 = i & 15;
            cpa16((uint32_t)__cvta_generic_to_shared(sv + r*SV2 + c4*4),
                  Vg + (size_t)r*SEQ + kt*ABN + c4*4);
        }
        asm volatile("cp.async.commit_group;\n" ::: "memory");
        asm volatile("cp.async.wait_group 0;\n" ::: "memory");
        __syncthreads();

        const int kcol_base = kt*ABN;
        if (kcol_base > qrow_base + 15) continue;

        float sacc[8][4];
#pragma unroll
        for (int i = 0; i < 8; i++)
#pragma unroll
            for (int j = 0; j < 4; j++) sacc[i][j] = 0.f;

#pragma unroll
        for (int kk = 0; kk < HD/16; kk++) {
            const uint32_t* qr = sq + (wid*16 + g)*SQ2 + kk*16 + 2*t4;
            uint2 ah02 = *(const uint2*)(qr);
            uint2 ah13 = *(const uint2*)(qr + 8*SQ2);
            uint2 al02 = *(const uint2*)(qr + 8);
            uint2 al13 = *(const uint2*)(qr + 8*SQ2 + 8);
#pragma unroll
            for (int nt = 0; nt < 8; nt++) {
                const uint32_t* kr = sk + (nt*8 + g)*SK2 + kk*16 + 2*t4;
                uint2 bhv = *(const uint2*)(kr);
                uint2 blv = *(const uint2*)(kr + 8);
                float* c = sacc[nt];
                mma_bf16(c, ah02.x, ah13.x, ah02.y, ah13.y, bhv.x, bhv.y);
                mma_bf16(c, ah02.x, ah13.x, ah02.y, ah13.y, blv.x, blv.y);
                mma_bf16(c, al02.x, al13.x, al02.y, al13.y, bhv.x, bhv.y);
            }
        }

        const bool need_mask = (kcol_base + ABN - 1) > qrow_base;
        float alpha2[2];
#pragma unroll
        for (int hh = 0; hh < 2; hh++) {
            const int qg = qrow_base + g + 8*hh;
            float mx = -1e30f;
#pragma unroll
            for (int nt = 0; nt < 8; nt++) {
#pragma unroll
                for (int j = 0; j < 2; j++) {
                    float s = sacc[nt][2*hh + j] * scale;
                    if (need_mask) {
                        int kg2 = kcol_base + nt*8 + 2*t4 + j;
                        if (kg2 > qg) s = -1e30f;
                    }
                    sacc[nt][2*hh + j] = s;
                    mx = fmaxf(mx, s);
                }
            }
            mx = fmaxf(mx, __shfl_xor_sync(0xffffffffu, mx, 1));
            mx = fmaxf(mx, __shfl_xor_sync(0xffffffffu, mx, 2));
            float mnew = fmaxf(mrow[hh], mx);
            float alpha = __expf(mrow[hh] - mnew);
            float sum = 0.f;
            const int prow = (wid*16 + g + 8*hh)*SP2;
#pragma unroll
            for (int nt = 0; nt < 8; nt++) {
                float p0 = __expf(sacc[nt][2*hh]     - mnew);
                float p1 = __expf(sacc[nt][2*hh + 1] - mnew);
                uint32_t hv, lv;
                split_bf16(p0, p1, hv, lv);
                int kp = nt*4 + t4;
                int cph = (kp >> 3)*16 + (kp & 7);
                sp[prow + cph]     = hv;
                sp[prow + cph + 8] = lv;
                sum += p0 + p1;
            }
            sum += __shfl_xor_sync(0xffffffffu, sum, 1);
            sum += __shfl_xor_sync(0xffffffffu, sum, 2);
            lrow[hh] = lrow[hh]*alpha + sum;
            mrow[hh] = mnew;
            alpha2[hh] = alpha;
        }

#pragma unroll
        for (int nt = 0; nt < 16; nt++) {
            o[nt][0] *= alpha2[0]; o[nt][1] *= alpha2[0];
            o[nt][2] *= alpha2[1]; o[nt][3] *= alpha2[1];
        }

        __syncwarp();

#pragma unroll
        for (int kk = 0; kk < ABN/16; kk++) {
            const uint32_t* pr = sp + (wid*16 + g)*SP2 + kk*16 + 2*t4;
            uint2 ah02 = *(const uint2*)(pr);
            uint2 ah13 = *(const uint2*)(pr + 8*SP2);
            uint2 al02 = *(const uint2*)(pr + 8);
            uint2 al13 = *(const uint2*)(pr + 8*SP2 + 8);
#pragma unroll
            for (int nt = 0; nt < 16; nt++) {
                const uint32_t* vr = sv + (nt*8 + g)*SV2 + kk*16 + 2*t4;
                uint2 bhv = *(const uint2*)(vr);
                uint2 blv = *(const uint2*)(vr + 8);
                float* c = o[nt];
                mma_bf16(c, ah02.x, ah13.x, ah02.y, ah13.y, bhv.x, bhv.y);
                mma_bf16(c, ah02.x, ah13.x, ah02.y, ah13.y, blv.x, blv.y);
                mma_bf16(c, al02.x, al13.x, al02.y, al13.y, bhv.x, bhv.y);
            }
        }
    }

    // epilogue: write output directly pre-split in flat hi/lo format
    const float inv0 = 1.f / lrow[0];
    const float inv1 = 1.f / lrow[1];
    const int r0 = qt*ABM + wid*16 + g;
    const size_t grow0 = (size_t)(b*SEQ + r0) * HID;
    const size_t grow1 = grow0 + 8*(size_t)HID;
#pragma unroll
    for (int nt = 0; nt < 16; nt++) {
        int colg = h*HD + nt*8 + 2*t4;
        int kg = colg >> 4;
        int p  = (colg >> 1) & 7;
        size_t i0 = grow0 + kg*16 + p;
        size_t i1 = grow1 + kg*16 + p;
        uint32_t h0, l0, h1, l1;
        split_bf16(o[nt][0]*inv0, o[nt][1]*inv0, h0, l0);
        split_bf16(o[nt][2]*inv1, o[nt][3]*inv1, h1, l1);
        As_out[i0]     = h0;
        As_out[i0 + 8] = l0;
        As_out[i1]     = h1;
        As_out[i1 + 8] = l1;
    }
}

// ---------------------------------------------------------------------------
// Launch.
// ---------------------------------------------------------------------------
extern "C" void kernel_launch(void* const* d_in, const int* in_sizes, int n_in,
                              void* d_out, int out_size)
{
    const void* slot[12];
    if (n_in >= 12 && in_sizes[0] == (int)(TOK*(size_t)HID)) {
        for (int i = 0; i < 12; i++) slot[i] = d_in[i];
    } else {
        // alphabetical: cos,k_b,k_w,kv_buffer,o_w,q_b,q_w,select_index,sin,v_b,v_w,x
        slot[8]  = d_in[0];
        slot[4]  = d_in[1];
        slot[3]  = d_in[2];
        slot[10] = d_in[3];
        slot[7]  = d_in[4];
        slot[2]  = d_in[5];
        slot[1]  = d_in[6];
        slot[11] = d_in[7];
        slot[9]  = d_in[8];
        slot[6]  = d_in[9];
        slot[5]  = d_in[10];
        slot[0]  = d_in[11];
    }

    const float* x     = (const float*)slot[0];
    const float* q_w   = (const float*)slot[1];
    const float* q_b   = (const float*)slot[2];
    const float* k_w   = (const float*)slot[3];
    const float* k_b   = (const float*)slot[4];
    const float* v_w   = (const float*)slot[5];
    const float* v_b   = (const float*)slot[6];
    const float* o_w   = (const float*)slot[7];
    const float* cosb  = (const float*)slot[8];
    const float* sinb  = (const float*)slot[9];
    const float* kvbuf = (const float*)slot[10];
    const void*  sel   = slot[11];

    float* out = (float*)d_out;
    bool has_buf = (size_t)out_size >= OUT_ELEMS + BUF_ELEMS;
    float* buf_out = out + ((size_t)out_size - BUF_ELEMS);

    float *Q, *K, *V;
    uint32_t *xs, *qws, *kws, *vws, *ows, *As, *Qsp, *Ksp, *Vtp;
    cudaGetSymbolAddress((void**)&Q, g_Q);
    cudaGetSymbolAddress((void**)&K, g_K);
    cudaGetSymbolAddress((void**)&V, g_V);
    cudaGetSymbolAddress((void**)&xs, g_xs);
    cudaGetSymbolAddress((void**)&qws, g_qws);
    cudaGetSymbolAddress((void**)&kws, g_kws);
    cudaGetSymbolAddress((void**)&vws, g_vws);
    cudaGetSymbolAddress((void**)&ows, g_ows);
    cudaGetSymbolAddress((void**)&As, g_As);
    cudaGetSymbolAddress((void**)&Qsp, g_Qs);
    cudaGetSymbolAddress((void**)&Ksp, g_Ks);
    cudaGetSymbolAddress((void**)&Vtp, g_Vt);

    // Pre-split inputs
    presplit_kernel<<<(TOK*HID/8 + 255)/256, 256>>>(x, xs, TOK*HID/8);
    presplit_kernel<<<(HID*HID/8 + 255)/256, 256>>>(q_w, qws, HID*HID/8);
    presplit_kernel<<<(KVDIM*HID/8 + 255)/256, 256>>>(k_w, kws, KVDIM*HID/8);
    presplit_kernel<<<(KVDIM*HID/8 + 255)/256, 256>>>(v_w, vws, KVDIM*HID/8);
    presplit_kernel<<<(HID*HID/8 + 255)/256, 256>>>(o_w, ows, HID*HID/8);

    cudaFuncSetAttribute(gemm_ps_kernel,
                         cudaFuncAttributeMaxDynamicSharedMemorySize, GEMM_SMEM);

    // Projections
    gemm_ps_kernel<<<dim3(HID/128, TOK/128, 1), 256, GEMM_SMEM>>>(
        xs, qws, q_b, Q, qws, q_b, Q, HID);
    gemm_ps_kernel<<<dim3(KVDIM/128, TOK/128, 2), 256, GEMM_SMEM>>>(
        xs, kws, k_b, K, vws, v_b, V, KVDIM);

    // RoPE + pre-split Q/K; V transpose + pre-split
    rope_split_kernel<<<dim3(TOK, NHEAD + NKV), 64>>>(Q, K, cosb, sinb, Qsp, Ksp);
    vt_kernel<<<dim3(SEQ/64, BATCH*NKV), 256>>>(V, Vtp);

    // KV buffer output
    if (has_buf) {
        cudaMemcpyAsync(buf_out, kvbuf, BUF_ELEMS * sizeof(float),
                        cudaMemcpyDeviceToDevice);
        scatter_kernel<<<TOK, 128>>>(K, V, sel, buf_out);
    }

    // Attention (writes pre-split output for O-proj)
    cudaFuncSetAttribute(attn_ps_kernel,
                         cudaFuncAttributeMaxDynamicSharedMemorySize,
                         (int)ATTN_SMEM);
    attn_ps_kernel<<<dim3(SEQ/ABM, BATCH*NHEAD), 256, ATTN_SMEM>>>(Qsp, Ksp, Vtp, As);

    // O projection
    gemm_ps_kernel<<<dim3(HID/128, TOK/128, 1), 256, GEMM_SMEM>>>(
        As, ows, nullptr, out, ows, nullptr, out, HID);
}

// round 16
// speedup vs baseline: 1.5074x; 1.0458x over previous
#include <cuda_runtime.h>
#include <cuda_bf16.h>
#include <cstdint>

// Problem constants
#define BATCH 4
#define SEQ   1024
#define HID   2048
#define NHEAD 16
#define NKV   2
#define HD    128
#define TOK   (BATCH*SEQ)          // 4096
#define KVDIM (NKV*HD)             // 256
#define OUT_ELEMS ((size_t)TOK*HID)
#define BUF_ELEMS ((size_t)2*TOK*2*NKV*HD)

// Scratch (device globals — no allocation allowed)
__device__ float g_Q[TOK*HID];
__device__ float g_K[TOK*KVDIM];
__device__ float g_V[TOK*KVDIM];
// pre-split (packed bf16 hi|lo) operands, flat format:
// per row, per 16-float k-group: [hi p0..p7][lo p0..p7] (16 u32)
__device__ uint32_t g_xs[TOK*HID];
__device__ uint32_t g_qws[HID*HID];
__device__ uint32_t g_kws[KVDIM*HID];
__device__ uint32_t g_vws[KVDIM*HID];
__device__ uint32_t g_ows[HID*HID];
__device__ uint32_t g_As[TOK*HID];      // attention output, written pre-split
// pre-split attention operands
__device__ uint32_t g_Qs[TOK*HID];
__device__ uint32_t g_Ks[TOK*KVDIM];
__device__ uint32_t g_Vt[(size_t)BATCH*NKV*HD*SEQ];

// ---------------------------------------------------------------------------
// bf16 split helpers
// ---------------------------------------------------------------------------
__device__ __forceinline__ void split_bf16(float x0, float x1,
                                           uint32_t& hi, uint32_t& lo)
{
    asm("cvt.rn.bf16x2.f32 %0, %1, %2;" : "=r"(hi) : "f"(x1), "f"(x0));
    float h0 = __uint_as_float(hi << 16);
    float h1 = __uint_as_float(hi & 0xffff0000u);
    asm("cvt.rn.bf16x2.f32 %0, %1, %2;" : "=r"(lo) : "f"(x1 - h1), "f"(x0 - h0));
}

__device__ __forceinline__ void mma_bf16(float c[4],
    uint32_t a0, uint32_t a1, uint32_t a2, uint32_t a3,
    uint32_t b0, uint32_t b1)
{
    asm volatile(
        "mma.sync.aligned.m16n8k16.row.col.f32.bf16.bf16.f32 "
        "{%0,%1,%2,%3}, {%4,%5,%6,%7}, {%8,%9}, {%0,%1,%2,%3};"
        : "+f"(c[0]), "+f"(c[1]), "+f"(c[2]), "+f"(c[3])
        : "r"(a0), "r"(a1), "r"(a2), "r"(a3), "r"(b0), "r"(b1));
}

__device__ __forceinline__ void cpa16(uint32_t smem_addr, const void* gptr) {
    asm volatile("cp.async.ca.shared.global [%0], [%1], 16;\n"
                 :: "r"(smem_addr), "l"(gptr));
}

// ---------------------------------------------------------------------------
// Pre-split kernel: fp32 -> packed hi/lo flat layout.
// ---------------------------------------------------------------------------
__global__ void presplit_kernel(const float* __restrict__ src,
                                uint32_t* __restrict__ dst, int n8)
{
    int idx = blockIdx.x * blockDim.x + threadIdx.x;
    if (idx >= n8) return;
    const float4 v0 = *(const float4*)(src + (size_t)idx*8);
    const float4 v1 = *(const float4*)(src + (size_t)idx*8 + 4);
    uint4 h, l;
    split_bf16(v0.x, v0.y, h.x, l.x);
    split_bf16(v0.z, v0.w, h.y, l.y);
    split_bf16(v1.x, v1.y, h.z, l.z);
    split_bf16(v1.z, v1.w, h.w, l.w);
    size_t base = (size_t)(idx >> 1)*16 + (idx & 1)*4;
    *(uint4*)(dst + base)     = h;
    *(uint4*)(dst + base + 8) = l;
}

// ---------------------------------------------------------------------------
// GEMM-NT on pre-split operands, KT=32, 2-stage cp.async, 2 CTAs/SM.
// Up to 3 output sets selected by blockIdx.x thresholds (fused Q/K/V).
// ---------------------------------------------------------------------------
#define GST2 40
#define NK2 (HID/32)
#define GEMM_SMEM (2*2*128*GST2*4)   // 81920 bytes

__global__ __launch_bounds__(256, 2) void gemm_ps3_kernel(
    const uint32_t* __restrict__ A,
    const uint32_t* __restrict__ B0, const float* __restrict__ bias0,
    float* __restrict__ C0, int N0,
    const uint32_t* __restrict__ B1, const float* __restrict__ bias1,
    float* __restrict__ C1, int N1,
    const uint32_t* __restrict__ B2, const float* __restrict__ bias2,
    float* __restrict__ C2, int N2,
    int s1, int s2)
{
    extern __shared__ __align__(16) uint32_t dyn[];
    uint32_t* Asm = dyn;
    uint32_t* Bsm = dyn + 2*128*GST2;

    const int bx = blockIdx.x;
    const int set = (bx >= s1) + (bx >= s2);
    const uint32_t* B = set == 0 ? B0 : (set == 1 ? B1 : B2);
    const float* bias = set == 0 ? bias0 : (set == 1 ? bias1 : bias2);
    float* C          = set == 0 ? C0 : (set == 1 ? C1 : C2);
    const int N       = set == 0 ? N0 : (set == 1 ? N1 : N2);
    const int n0      = (bx - (set == 0 ? 0 : (set == 1 ? s1 : s2))) * 128;

    const int tid  = threadIdx.x;
    const int lane = tid & 31;
    const int wid  = tid >> 5;
    const int g    = lane >> 2;
    const int t4   = lane & 3;
    const int wm   = wid >> 2;
    const int wn   = wid & 3;

    const int m0 = blockIdx.y * 128;
    const int K  = HID;

    float acc[16][4];
#pragma unroll
    for (int i = 0; i < 16; i++)
#pragma unroll
        for (int j = 0; j < 4; j++) acc[i][j] = 0.f;

    auto issue = [&](int s, int it) {
#pragma unroll
        for (int rep = 0; rep < 8; rep++) {
            int j = rep*256 + tid;
            int arr = j >> 10;
            int i = j & 1023;
            int row = i >> 3, q = (i & 7)*4;
            const uint32_t* src = (arr ? (B + (size_t)(n0 + row)*K)
                                       : (A + (size_t)(m0 + row)*K))
                                  + it*32 + q;
            uint32_t* dstb = (arr ? Bsm : Asm) + s*128*GST2 + row*GST2 + q;
            cpa16((uint32_t)__cvta_generic_to_shared(dstb), src);
        }
        asm volatile("cp.async.commit_group;" ::: "memory");
    };

    issue(0, 0);

    for (int it = 0; it < NK2; it++) {
        const int cur = it & 1;
        if (it + 1 < NK2) {
            issue(cur ^ 1, it + 1);
            asm volatile("cp.async.wait_group 1;" ::: "memory");
        } else {
            asm volatile("cp.async.wait_group 0;" ::: "memory");
        }
        __syncthreads();

        const uint32_t* Asc = Asm + cur*128*GST2;
        const uint32_t* Bsc = Bsm + cur*128*GST2;

#pragma unroll
        for (int kg2 = 0; kg2 < 2; kg2++) {
            const int off = kg2*16;
            uint2 tah[4][2], tal[4][2];
#pragma unroll
            for (int mt = 0; mt < 4; mt++) {
                const uint32_t* ar = Asc + (wm*64 + mt*16 + g)*GST2 + off;
                tah[mt][0] = *(const uint2*)(ar + 2*t4);
                tah[mt][1] = *(const uint2*)(ar + 8*GST2 + 2*t4);
                tal[mt][0] = *(const uint2*)(ar + 8 + 2*t4);
                tal[mt][1] = *(const uint2*)(ar + 8*GST2 + 8 + 2*t4);
            }
#pragma unroll
            for (int nt = 0; nt < 4; nt++) {
                const uint32_t* br = Bsc + (wn*32 + nt*8 + g)*GST2 + off;
                uint2 bh = *(const uint2*)(br + 2*t4);
                uint2 bl = *(const uint2*)(br + 8 + 2*t4);
#pragma unroll
                for (int mt = 0; mt < 4; mt++) {
                    float* c = acc[mt*4 + nt];
                    mma_bf16(c, tah[mt][0].x, tah[mt][1].x, tah[mt][0].y, tah[mt][1].y, bh.x, bh.y);
                    mma_bf16(c, tah[mt][0].x, tah[mt][1].x, tah[mt][0].y, tah[mt][1].y, bl.x, bl.y);
                    mma_bf16(c, tal[mt][0].x, tal[mt][1].x, tal[mt][0].y, tal[mt][1].y, bh.x, bh.y);
                }
            }
        }
        __syncthreads();
    }

#pragma unroll
    for (int mt = 0; mt < 4; mt++) {
#pragma unroll
        for (int nt = 0; nt < 4; nt++) {
            const float* c = acc[mt*4 + nt];
            int row0 = m0 + wm*64 + mt*16 + g;
            int col  = n0 + wn*32 + nt*8 + 2*t4;
            float b0 = bias ? bias[col]     : 0.f;
            float b1 = bias ? bias[col + 1] : 0.f;
            float2 v0 = make_float2(c[0] + b0, c[1] + b1);
            float2 v1 = make_float2(c[2] + b0, c[3] + b1);
            *(float2*)(C + (size_t)row0 * N + col)       = v0;
            *(float2*)(C + (size_t)(row0 + 8) * N + col) = v1;
        }
    }
}

// ---------------------------------------------------------------------------
// RoPE + pre-split. Block (64,4): 4 tokens per block.
// ---------------------------------------------------------------------------
__global__ void rope_split_kernel(const float* __restrict__ Q,
                                  float* __restrict__ K,
                                  const float* __restrict__ cosb,
                                  const float* __restrict__ sinb,
                                  uint32_t* __restrict__ Qs,
                                  uint32_t* __restrict__ Ks)
{
    int t  = blockIdx.x*4 + threadIdx.y;
    int hy = blockIdx.y;
    int j  = threadIdx.x;
    int s  = t & (SEQ - 1);
    int f0 = 2*j;
    float c0 = cosb[s*HD + f0],     c1 = cosb[s*HD + f0 + 1];
    float s0 = sinb[s*HD + f0],     s1 = sinb[s*HD + f0 + 1];

    const float* src;
    float* wb = nullptr;
    uint32_t* dst;
    if (hy < NHEAD) {
        src = Q + (size_t)t*HID + hy*HD;
        dst = Qs + (size_t)t*HID + hy*HD;
    } else {
        float* kp = K + (size_t)t*KVDIM + (hy - NHEAD)*HD;
        src = kp; wb = kp;
        dst = Ks + (size_t)t*KVDIM + (hy - NHEAD)*HD;
    }

    float xa = src[f0], xb = src[f0 + 1];
    int pf = (j < 32) ? f0 + 64 : f0 - 64;
    float pa = src[pf], pb = src[pf + 1];
    __syncthreads();

    float r0 = (j < 32) ? -pa : pa;
    float r1 = (j < 32) ? -pb : pb;
    float o0 = xa*c0 + r0*s0;
    float o1 = xb*c1 + r1*s1;

    uint32_t h, l;
    split_bf16(o0, o1, h, l);
    int w = (j >> 3)*16 + (j & 7);
    dst[w]     = h;
    dst[w + 8] = l;
    if (wb) { wb[f0] = o0; wb[f0 + 1] = o1; }
}

// ---------------------------------------------------------------------------
// V transpose + pre-split. Per 16-key group: word order p0 p4 p1 p5 p2 p6 p3 p7
// (hi half; lo half at +8) so the b-frag uint2 read at 2*t4 delivers key pairs
// (t4, 4+t4) — matching the register-resident P a-fragments.
// ---------------------------------------------------------------------------
__global__ __launch_bounds__(256) void vt_kernel(const float* __restrict__ V,
                                                 uint32_t* __restrict__ Vt)
{
    __shared__ float ts[64*133];
    const int kc  = blockIdx.x;
    const int bh2 = blockIdx.y;
    const int b   = bh2 >> 1;
    const int kvh = bh2 & 1;
    const int tid = threadIdx.x;

    for (int i = tid; i < 64*32; i += 256) {
        int r = i >> 5, c4 = i & 31;
        float4 v = *(const float4*)(V + (size_t)(b*SEQ + kc*64 + r)*KVDIM
                                      + kvh*HD + c4*4);
        float* d = ts + r*133 + c4*4;
        d[0] = v.x; d[1] = v.y; d[2] = v.z; d[3] = v.w;
    }
    __syncthreads();

    uint32_t* out = Vt + (size_t)bh2*HD*SEQ + kc*64;
    for (int i = tid; i < 128*32; i += 256) {
        int d = i >> 5, l = i & 31;
        int w0 = 2*l;
        uint2 o;
#pragma unroll
        for (int e = 0; e < 2; e++) {
            int w = w0 + e, gi = w >> 4, ss = w & 15;
            int sh = ss & 7;                       // slot within hi/lo half
            int p  = (sh & 1) ? 4 + (sh >> 1) : (sh >> 1);   // permuted pair
            int lk = gi*16 + 2*p;                  // local key
            uint32_t h, lo;
            split_bf16(ts[lk*133 + d], ts[(lk+1)*133 + d], h, lo);
            uint32_t val = (ss < 8) ? h : lo;
            if (e == 0) o.x = val; else o.y = val;
        }
        *(uint2*)(out + (size_t)d*SEQ + w0) = o;
    }
}

// ---------------------------------------------------------------------------
// Scatter K/V into output kv buffer (unchanged)
// ---------------------------------------------------------------------------
__global__ void scatter_kernel(const float* __restrict__ K,
                               const float* __restrict__ V,
                               const void* __restrict__ idx,
                               float* __restrict__ buf)
{
    int t = blockIdx.x;
    int d = threadIdx.x;
    const long long* i64 = (const long long*)idx;
    const int*       i32 = (const int*)idx;
    bool is64 = ((unsigned long long)i64[1]) < (unsigned long long)(2*TOK);
    long long row = is64 ? i64[t] : (long long)i32[t];
    if (row < 0 || row >= (long long)(2*TOK)) return;
    size_t base = (size_t)row * 4 * HD;
    buf[base + 0*HD + d] = K[(size_t)t*KVDIM + d];
    buf[base + 1*HD + d] = K[(size_t)t*KVDIM + HD + d];
    buf[base + 2*HD + d] = V[(size_t)t*KVDIM + d];
    buf[base + 3*HD + d] = V[(size_t)t*KVDIM + HD + d];
}

// ---------------------------------------------------------------------------
// Tensor-core flash attention: P stays in registers (FA2 register reuse),
// K/V tiles double-buffered via cp.async ping-pong, heavy q-tiles first.
// ---------------------------------------------------------------------------
#define ABM 128
#define ABN 64
#define SQ2 136
#define SK2 136
#define SV2 72
#define STAGE_U32 (ABN*SK2 + ABM*SV2)
#define ATTN_SMEM ((ABM*SQ2 + 2*STAGE_U32) * sizeof(uint32_t))   // 212992 B

__global__ __launch_bounds__(256, 1) void attn_ps_kernel(
    const uint32_t* __restrict__ Qs, const uint32_t* __restrict__ Ks,
    const uint32_t* __restrict__ Vt, uint32_t* __restrict__ As_out)
{
    extern __shared__ __align__(16) uint32_t smu[];
    uint32_t* sq = smu;                         // 128 x 136

    const int bh  = blockIdx.y;
    const int b   = bh / NHEAD;
    const int h   = bh % NHEAD;
    const int kvh = h / (NHEAD / NKV);
    const int qt  = gridDim.x - 1 - blockIdx.x;   // heavy tiles first
    const int tid = threadIdx.x;
    const int lane = tid & 31;
    const int wid  = tid >> 5;
    const int g    = lane >> 2;
    const int t4   = lane & 3;
    const float scale = 0.08838834764831845f;

    const int nkt = 2*qt + 2;
    const uint32_t* Vg = Vt + (size_t)(b*NKV + kvh)*HD*SEQ;
    const uint32_t* Kg = Ks + (size_t)(b*SEQ)*KVDIM + kvh*HD;

    auto issue = [&](int s, int kt) {
        uint32_t* sk = smu + ABM*SQ2 + s*STAGE_U32;
        uint32_t* sv = sk + ABN*SK2;
        for (int i = tid; i < ABN*32; i += 256) {
            int r = i >> 5, c4 = i & 31;
            cpa16((uint32_t)__cvta_generic_to_shared(sk + r*SK2 + c4*4),
                  Kg + (size_t)(kt*ABN + r)*KVDIM + c4*4);
        }
        for (int i = tid; i < ABM*16; i += 256) {
            int r = i >> 4, c4 = i & 15;
            cpa16((uint32_t)__cvta_generic_to_shared(sv + r*SV2 + c4*4),
                  Vg + (size_t)r*SEQ + kt*ABN + c4*4);
        }
        asm volatile("cp.async.commit_group;" ::: "memory");
    };

    issue(0, 0);

    // load pre-split Q tile (overlaps with first K/V load)
    const uint32_t* Qg = Qs + (size_t)(b*SEQ + qt*ABM)*HID + h*HD;
    for (int i = tid; i < ABM*32; i += 256) {
        int r = i >> 5, c4 = i & 31;
        *(uint4*)(sq + r*SQ2 + c4*4) = *(const uint4*)(Qg + (size_t)r*HID + c4*4);
    }

    float o[16][4];
#pragma unroll
    for (int i = 0; i < 16; i++)
#pragma unroll
        for (int j = 0; j < 4; j++) o[i][j] = 0.f;
    float mrow[2] = {-1e30f, -1e30f};
    float lrow[2] = {0.f, 0.f};

    const int qrow_base = qt*ABM + wid*16;

    for (int kt = 0; kt < nkt; kt++) {
        const int cur = kt & 1;
        if (kt + 1 < nkt) {
            issue(cur ^ 1, kt + 1);
            asm volatile("cp.async.wait_group 1;" ::: "memory");
        } else {
            asm volatile("cp.async.wait_group 0;" ::: "memory");
        }
        __syncthreads();

        const uint32_t* sk = smu + ABM*SQ2 + cur*STAGE_U32;
        const uint32_t* sv = sk + ABN*SK2;
        const int kcol_base = kt*ABN;
        const bool active = kcol_base <= qrow_base + 15;

        if (active) {
            // ---- S = Q K^T ----
            float sacc[8][4];
#pragma unroll
            for (int i = 0; i < 8; i++)
#pragma unroll
                for (int j = 0; j < 4; j++) sacc[i][j] = 0.f;

#pragma unroll
            for (int kk = 0; kk < HD/16; kk++) {
                const uint32_t* qr = sq + (wid*16 + g)*SQ2 + kk*16 + 2*t4;
                uint2 ah02 = *(const uint2*)(qr);
                uint2 ah13 = *(const uint2*)(qr + 8*SQ2);
                uint2 al02 = *(const uint2*)(qr + 8);
                uint2 al13 = *(const uint2*)(qr + 8*SQ2 + 8);
#pragma unroll
                for (int nt = 0; nt < 8; nt++) {
                    const uint32_t* kr = sk + (nt*8 + g)*SK2 + kk*16 + 2*t4;
                    uint2 bhv = *(const uint2*)(kr);
                    uint2 blv = *(const uint2*)(kr + 8);
                    float* c = sacc[nt];
                    mma_bf16(c, ah02.x, ah13.x, ah02.y, ah13.y, bhv.x, bhv.y);
                    mma_bf16(c, ah02.x, ah13.x, ah02.y, ah13.y, blv.x, blv.y);
                    mma_bf16(c, al02.x, al13.x, al02.y, al13.y, bhv.x, bhv.y);
                }
            }

            // ---- mask + online softmax; P split into registers ----
            const bool need_mask = (kcol_base + ABN - 1) > qrow_base;
            uint32_t ph[8][2], pl[8][2];
            float alpha2[2];
#pragma unroll
            for (int hh = 0; hh < 2; hh++) {
                const int qg = qrow_base + g + 8*hh;
                float mx = -1e30f;
#pragma unroll
                for (int nt = 0; nt < 8; nt++) {
#pragma unroll
                    for (int j = 0; j < 2; j++) {
                        float s = sacc[nt][2*hh + j] * scale;
                        if (need_mask) {
                            int kg2 = kcol_base + nt*8 + 2*t4 + j;
                            if (kg2 > qg) s = -1e30f;
                        }
                        sacc[nt][2*hh + j] = s;
                        mx = fmaxf(mx, s);
                    }
                }
                mx = fmaxf(mx, __shfl_xor_sync(0xffffffffu, mx, 1));
                mx = fmaxf(mx, __shfl_xor_sync(0xffffffffu, mx, 2));
                float mnew = fmaxf(mrow[hh], mx);
                float alpha = __expf(mrow[hh] - mnew);
                float sum = 0.f;
#pragma unroll
                for (int nt = 0; nt < 8; nt++) {
                    float p0 = __expf(sacc[nt][2*hh]     - mnew);
                    float p1 = __expf(sacc[nt][2*hh + 1] - mnew);
                    split_bf16(p0, p1, ph[nt][hh], pl[nt][hh]);
                    sum += p0 + p1;
                }
                sum += __shfl_xor_sync(0xffffffffu, sum, 1);
                sum += __shfl_xor_sync(0xffffffffu, sum, 2);
                lrow[hh] = lrow[hh]*alpha + sum;
                mrow[hh] = mnew;
                alpha2[hh] = alpha;
            }

#pragma unroll
            for (int nt = 0; nt < 16; nt++) {
                o[nt][0] *= alpha2[0]; o[nt][1] *= alpha2[0];
                o[nt][2] *= alpha2[1]; o[nt][3] *= alpha2[1];
            }

            // ---- O += P V (P a-frags direct from registers) ----
#pragma unroll
            for (int kk = 0; kk < ABN/16; kk++) {
                const uint32_t a0h = ph[2*kk][0],   a1h = ph[2*kk][1];
                const uint32_t a2h = ph[2*kk+1][0], a3h = ph[2*kk+1][1];
                const uint32_t a0l = pl[2*kk][0],   a1l = pl[2*kk][1];
                const uint32_t a2l = pl[2*kk+1][0], a3l = pl[2*kk+1][1];
#pragma unroll
                for (int nt = 0; nt < 16; nt++) {
                    const uint32_t* vr = sv + (nt*8 + g)*SV2 + kk*16 + 2*t4;
                    uint2 bhv = *(const uint2*)(vr);
                    uint2 blv = *(const uint2*)(vr + 8);
                    float* c = o[nt];
                    mma_bf16(c, a0h, a1h, a2h, a3h, bhv.x, bhv.y);
                    mma_bf16(c, a0h, a1h, a2h, a3h, blv.x, blv.y);
                    mma_bf16(c, a0l, a1l, a2l, a3l, bhv.x, bhv.y);
                }
            }
        }
        __syncthreads();
    }

    // epilogue: write output directly pre-split in flat hi/lo format
    const float inv0 = 1.f / lrow[0];
    const float inv1 = 1.f / lrow[1];
    const int r0 = qt*ABM + wid*16 + g;
    const size_t grow0 = (size_t)(b*SEQ + r0) * HID;
    const size_t grow1 = grow0 + 8*(size_t)HID;
#pragma unroll
    for (int nt = 0; nt < 16; nt++) {
        int colg = h*HD + nt*8 + 2*t4;
        int kg = colg >> 4;
        int p  = (colg >> 1) & 7;
        size_t i0 = grow0 + kg*16 + p;
        size_t i1 = grow1 + kg*16 + p;
        uint32_t h0, l0, h1, l1;
        split_bf16(o[nt][0]*inv0, o[nt][1]*inv0, h0, l0);
        split_bf16(o[nt][2]*inv1, o[nt][3]*inv1, h1, l1);
        As_out[i0]     = h0;
        As_out[i0 + 8] = l0;
        As_out[i1]     = h1;
        As_out[i1 + 8] = l1;
    }
}

// ---------------------------------------------------------------------------
// Launch.
// ---------------------------------------------------------------------------
extern "C" void kernel_launch(void* const* d_in, const int* in_sizes, int n_in,
                              void* d_out, int out_size)
{
    const void* slot[12];
    if (n_in >= 12 && in_sizes[0] == (int)(TOK*(size_t)HID)) {
        for (int i = 0; i < 12; i++) slot[i] = d_in[i];
    } else {
        // alphabetical: cos,k_b,k_w,kv_buffer,o_w,q_b,q_w,select_index,sin,v_b,v_w,x
        slot[8]  = d_in[0];
        slot[4]  = d_in[1];
        slot[3]  = d_in[2];
        slot[10] = d_in[3];
        slot[7]  = d_in[4];
        slot[2]  = d_in[5];
        slot[1]  = d_in[6];
        slot[11] = d_in[7];
        slot[9]  = d_in[8];
        slot[6]  = d_in[9];
        slot[5]  = d_in[10];
        slot[0]  = d_in[11];
    }

    const float* x     = (const float*)slot[0];
    const float* q_w   = (const float*)slot[1];
    const float* q_b   = (const float*)slot[2];
    const float* k_w   = (const float*)slot[3];
    const float* k_b   = (const float*)slot[4];
    const float* v_w   = (const float*)slot[5];
    const float* v_b   = (const float*)slot[6];
    const float* o_w   = (const float*)slot[7];
    const float* cosb  = (const float*)slot[8];
    const float* sinb  = (const float*)slot[9];
    const float* kvbuf = (const float*)slot[10];
    const void*  sel   = slot[11];

    float* out = (float*)d_out;
    bool has_buf = (size_t)out_size >= OUT_ELEMS + BUF_ELEMS;
    float* buf_out = out + ((size_t)out_size - BUF_ELEMS);

    float *Q, *K, *V;
    uint32_t *xs, *qws, *kws, *vws, *ows, *As, *Qsp, *Ksp, *Vtp;
    cudaGetSymbolAddress((void**)&Q, g_Q);
    cudaGetSymbolAddress((void**)&K, g_K);
    cudaGetSymbolAddress((void**)&V, g_V);
    cudaGetSymbolAddress((void**)&xs, g_xs);
    cudaGetSymbolAddress((void**)&qws, g_qws);
    cudaGetSymbolAddress((void**)&kws, g_kws);
    cudaGetSymbolAddress((void**)&vws, g_vws);
    cudaGetSymbolAddress((void**)&ows, g_ows);
    cudaGetSymbolAddress((void**)&As, g_As);
    cudaGetSymbolAddress((void**)&Qsp, g_Qs);
    cudaGetSymbolAddress((void**)&Ksp, g_Ks);
    cudaGetSymbolAddress((void**)&Vtp, g_Vt);

    // Pre-split inputs
    presplit_kernel<<<(TOK*HID/8 + 255)/256, 256>>>(x, xs, TOK*HID/8);
    presplit_kernel<<<(HID*HID/8 + 255)/256, 256>>>(q_w, qws, HID*HID/8);
    presplit_kernel<<<(KVDIM*HID/8 + 255)/256, 256>>>(k_w, kws, KVDIM*HID/8);
    presplit_kernel<<<(KVDIM*HID/8 + 255)/256, 256>>>(v_w, vws, KVDIM*HID/8);
    presplit_kernel<<<(HID*HID/8 + 255)/256, 256>>>(o_w, ows, HID*HID/8);

    cudaFuncSetAttribute(gemm_ps3_kernel,
                         cudaFuncAttributeMaxDynamicSharedMemorySize, GEMM_SMEM);

    // Fused Q/K/V projections: bx 0-15 Q, 16-17 K, 18-19 V
    gemm_ps3_kernel<<<dim3(20, TOK/128, 1), 256, GEMM_SMEM>>>(
        xs,
        qws, q_b, Q, HID,
        kws, k_b, K, KVDIM,
        vws, v_b, V, KVDIM,
        16, 18);

    // RoPE + pre-split Q/K; V transpose + pre-split
    rope_split_kernel<<<dim3(TOK/4, NHEAD + NKV), dim3(64, 4)>>>(
        Q, K, cosb, sinb, Qsp, Ksp);
    vt_kernel<<<dim3(SEQ/64, BATCH*NKV), 256>>>(V, Vtp);

    // KV buffer output
    if (has_buf) {
        cudaMemcpyAsync(buf_out, kvbuf, BUF_ELEMS * sizeof(float),
                        cudaMemcpyDeviceToDevice);
        scatter_kernel<<<TOK, 128>>>(K, V, sel, buf_out);
    }

    // Attention
    cudaFuncSetAttribute(attn_ps_kernel,
                         cudaFuncAttributeMaxDynamicSharedMemorySize,
                         (int)ATTN_SMEM);
    attn_ps_kernel<<<dim3(SEQ/ABM, BATCH*NHEAD), 256, ATTN_SMEM>>>(Qsp, Ksp, Vtp, As);

    // O projection
    gemm_ps3_kernel<<<dim3(16, TOK/128, 1), 256, GEMM_SMEM>>>(
        As,
        ows, nullptr, out, HID,
        ows, nullptr, out, HID,
        ows, nullptr, out, HID,
        16, 17);
}